// round 8
// baseline (speedup 1.0000x reference)
#include <cuda_runtime.h>
#include <cuda_bf16.h>
#include <math.h>
#include <stdint.h>

// Problem constants
constexpr int C_B    = 2;
constexpr int C_T    = 2048;
constexpr int C_HID  = 2048;
constexpr int C_H    = 16;
constexpr int C_D    = 128;
constexpr int C_WIN  = 512;
constexpr int C_QC   = 512;
constexpr int C_G    = 4;
constexpr int C_INTER= 2048;
constexpr int C_TOK  = C_B * C_T;

// ---------------------------------------------------------------------------
// Scratch (device globals)
// ---------------------------------------------------------------------------
__device__ __nv_bfloat16 g_h_bh [C_TOK * C_HID];
__device__ __nv_bfloat16 g_h_bl [C_TOK * C_HID];
__device__ __nv_bfloat16 g_hc_bh[C_TOK * C_QC];
__device__ __nv_bfloat16 g_hc_bl[C_TOK * C_QC];
__device__ float g_q  [C_TOK * C_H * C_D];
__device__ float g_kv [C_TOK * 2 * C_D];
__device__ float g_att[C_TOK * C_H * C_D];
__device__ float g_y1 [C_TOK * C_G * C_INTER];
// Transposed weights
__device__ __nv_bfloat16 g_wqcT_bh[C_QC * C_HID];
__device__ __nv_bfloat16 g_wqcT_bl[C_QC * C_HID];
__device__ __nv_bfloat16 g_wquT_bh[C_H * C_D * C_QC];
__device__ __nv_bfloat16 g_wquT_bl[C_H * C_D * C_QC];
__device__ __nv_bfloat16 g_wkvT_bh[2 * C_D * C_HID];
__device__ __nv_bfloat16 g_wkvT_bl[2 * C_D * C_HID];
__device__ float g_w1T [C_G * C_INTER * (C_H / C_G) * C_D];
__device__ float g_w2T [C_HID * C_G * C_INTER];

__device__ __forceinline__ uint32_t f2tf32(float f) {
    uint32_t r;
    asm("cvt.rna.tf32.f32 %0, %1;" : "=r"(r) : "f"(f));
    return r;
}
__device__ __forceinline__ float tf32r(float f) { return __uint_as_float(f2tf32(f)); }

__device__ __forceinline__ void mma_tf32(float& c0, float& c1, float& c2, float& c3,
                                         uint32_t a0, uint32_t a1, uint32_t a2, uint32_t a3,
                                         uint32_t b0, uint32_t b1) {
    asm volatile(
        "mma.sync.aligned.m16n8k8.row.col.f32.tf32.tf32.f32 "
        "{%0,%1,%2,%3}, {%4,%5,%6,%7}, {%8,%9}, {%0,%1,%2,%3};"
        : "+f"(c0), "+f"(c1), "+f"(c2), "+f"(c3)
        : "r"(a0), "r"(a1), "r"(a2), "r"(a3), "r"(b0), "r"(b1));
}

__device__ __forceinline__ void mma_bf16(float& c0, float& c1, float& c2, float& c3,
                                         uint32_t a0, uint32_t a1, uint32_t a2, uint32_t a3,
                                         uint32_t b0, uint32_t b1) {
    asm volatile(
        "mma.sync.aligned.m16n8k16.row.col.f32.bf16.bf16.f32 "
        "{%0,%1,%2,%3}, {%4,%5,%6,%7}, {%8,%9}, {%0,%1,%2,%3};"
        : "+f"(c0), "+f"(c1), "+f"(c2), "+f"(c3)
        : "r"(a0), "r"(a1), "r"(a2), "r"(a3), "r"(b0), "r"(b1));
}

__device__ __forceinline__ void ldsm4(uint32_t& r0, uint32_t& r1, uint32_t& r2, uint32_t& r3,
                                      uint32_t addr) {
    asm volatile("ldmatrix.sync.aligned.m8n8.x4.shared.b16 {%0,%1,%2,%3}, [%4];"
                 : "=r"(r0), "=r"(r1), "=r"(r2), "=r"(r3) : "r"(addr));
}

__device__ __forceinline__ void cp_async16(uint32_t saddr, const void* g) {
    asm volatile("cp.async.cg.shared.global [%0], [%1], 16;\n" :: "r"(saddr), "l"(g));
}
__device__ __forceinline__ void cp_commit() { asm volatile("cp.async.commit_group;\n"); }
template<int N>
__device__ __forceinline__ void cp_wait() { asm volatile("cp.async.wait_group %0;\n" :: "n"(N)); }

// ---------------------------------------------------------------------------
// bf16 3-term GEMM (hi/lo split): C = (Ah+Al)(Bh+Bl) ~ Ah·Bh + Al·Bh + Ah·Bl
// A [M][K] bf16 row-major, B [N][K] bf16 (k-contiguous). BK=64. S=2 stages.
// EPI: 0 = fp32 C; 3 = bf16 hi/lo (Cb, Cb2).
// ---------------------------------------------------------------------------
template<int EPI, int BM>
__global__ void __launch_bounds__(BM * 4)
gemm_bf16(const __nv_bfloat16* __restrict__ Ah, const __nv_bfloat16* __restrict__ Al,
          const __nv_bfloat16* __restrict__ Bh, const __nv_bfloat16* __restrict__ Bl,
          float* __restrict__ C, __nv_bfloat16* __restrict__ Cb,
          __nv_bfloat16* __restrict__ Cb2,
          int K, int lda, int ldb, int ldc) {
    constexpr int BK     = 64;                  // bf16 elems (128B rows)
    constexpr int LDRB   = 144;                 // bytes per smem row (16B stagger)
    constexpr int THREADS= BM * 4;
    constexpr int APB    = BM  * LDRB;
    constexpr int BPB    = 128 * LDRB;
    constexpr int S      = 2;
    constexpr int STAGEB = 2 * (APB + BPB);
    constexpr int A_IT   = (BM * 8) / THREADS;
    constexpr int B_IT   = 1024 / THREADS;

    extern __shared__ char smc[];
    const uint32_t sbase = (uint32_t)__cvta_generic_to_shared(smc);

    const int tid  = threadIdx.x;
    const int warp = tid >> 5;
    const int lane = tid & 31;
    const int wm   = (warp >> 2) * 32;
    const int wn   = (warp & 3) * 32;
    const int grp  = lane >> 2;
    const int tig  = lane & 3;

    const int arow   = lane & 15;
    const int aoff16 = (lane >> 4) * 16;
    const int bsel   = (lane >> 4) & 1;
    const int boff16 = ((lane >> 3) & 1) * 16;
    const int brow   = lane & 7;

    const __nv_bfloat16* Ahb = Ah + (size_t)blockIdx.y * BM * lda;
    const __nv_bfloat16* Alb = Al + (size_t)blockIdx.y * BM * lda;
    const __nv_bfloat16* Bhb = Bh + (size_t)blockIdx.x * 128 * ldb;
    const __nv_bfloat16* Blb = Bl + (size_t)blockIdx.x * 128 * ldb;

    float acc[2][4][4];
#pragma unroll
    for (int i = 0; i < 2; i++)
#pragma unroll
        for (int j = 0; j < 4; j++)
#pragma unroll
            for (int r = 0; r < 4; r++) acc[i][j][r] = 0.f;

    auto issue = [&](int kt) {
        const int k0 = kt * BK;
        const uint32_t sa = sbase + (uint32_t)((kt & 1) * STAGEB);
#pragma unroll
        for (int i = 0; i < A_IT; i++) {
            int c = tid + i * THREADS;
            int m = c >> 3, kc = c & 7;
            uint32_t d = sa + (uint32_t)(m * LDRB + kc * 16);
            const size_t go = (size_t)m * lda + k0 + kc * 8;
            cp_async16(d, Ahb + go);
            cp_async16(d + (APB + BPB), Alb + go);
        }
#pragma unroll
        for (int i = 0; i < B_IT; i++) {
            int c = tid + i * THREADS;
            int n = c >> 3, kc = c & 7;
            uint32_t d = sa + APB + (uint32_t)(n * LDRB + kc * 16);
            const size_t go = (size_t)n * ldb + k0 + kc * 8;
            cp_async16(d, Bhb + go);
            cp_async16(d + (APB + BPB), Blb + go);
        }
        cp_commit();
    };

    auto compute = [&](int kt) {
        const uint32_t stb   = sbase + (uint32_t)((kt & 1) * STAGEB);
        const uint32_t a_hi0 = stb + (uint32_t)(wm + arow) * LDRB + aoff16;
        const uint32_t b_hi0 = stb + APB + (uint32_t)(wn + bsel * 8 + brow) * LDRB + boff16;
#pragma unroll
        for (int ks = 0; ks < 4; ks++) {
            const uint32_t kb = ks * 32;   // 16 bf16 * 2B
            uint32_t ah[2][4], bh[2][4], al[2][4], bl[2][4];
#pragma unroll
            for (int mi = 0; mi < 2; mi++) {
                ldsm4(ah[mi][0], ah[mi][1], ah[mi][2], ah[mi][3],
                      a_hi0 + mi * (16 * LDRB) + kb);
                ldsm4(al[mi][0], al[mi][1], al[mi][2], al[mi][3],
                      a_hi0 + (APB + BPB) + mi * (16 * LDRB) + kb);
            }
#pragma unroll
            for (int p = 0; p < 2; p++) {
                ldsm4(bh[p][0], bh[p][1], bh[p][2], bh[p][3],
                      b_hi0 + p * (16 * LDRB) + kb);
                ldsm4(bl[p][0], bl[p][1], bl[p][2], bl[p][3],
                      b_hi0 + (APB + BPB) + p * (16 * LDRB) + kb);
            }
#pragma unroll
            for (int mi = 0; mi < 2; mi++)
#pragma unroll
                for (int ni = 0; ni < 4; ni++) {
                    const int p = ni >> 1, q = (ni & 1) * 2;
                    mma_bf16(acc[mi][ni][0], acc[mi][ni][1], acc[mi][ni][2], acc[mi][ni][3],
                             ah[mi][0], ah[mi][1], ah[mi][2], ah[mi][3],
                             bh[p][q], bh[p][q + 1]);
                    mma_bf16(acc[mi][ni][0], acc[mi][ni][1], acc[mi][ni][2], acc[mi][ni][3],
                             al[mi][0], al[mi][1], al[mi][2], al[mi][3],
                             bh[p][q], bh[p][q + 1]);
                    mma_bf16(acc[mi][ni][0], acc[mi][ni][1], acc[mi][ni][2], acc[mi][ni][3],
                             ah[mi][0], ah[mi][1], ah[mi][2], ah[mi][3],
                             bl[p][q], bl[p][q + 1]);
                }
        }
    };

    const int KT = K / BK;
    issue(0);
    if (KT > 1) issue(1); else cp_commit();
    for (int kt = 0; kt < KT; kt++) {
        cp_wait<S - 1>();
        __syncthreads();
        compute(kt);
        __syncthreads();
        if (kt + S < KT) issue(kt + S); else cp_commit();
    }

#pragma unroll
    for (int mi = 0; mi < 2; mi++) {
        int m0 = blockIdx.y * BM + wm + mi * 16 + grp;
#pragma unroll
        for (int ni = 0; ni < 4; ni++) {
            int n = blockIdx.x * 128 + wn + ni * 8 + tig * 2;
#pragma unroll
            for (int half = 0; half < 2; half++) {
                size_t off = (size_t)(m0 + half * 8) * ldc + n;
                float v0 = acc[mi][ni][half * 2], v1 = acc[mi][ni][half * 2 + 1];
                if (EPI == 0) {
                    *(float2*)(C + off) = make_float2(v0, v1);
                } else {
                    __nv_bfloat16 h0 = __float2bfloat16_rn(v0);
                    __nv_bfloat16 h1 = __float2bfloat16_rn(v1);
                    __nv_bfloat162 hh; hh.x = h0; hh.y = h1;
                    *(__nv_bfloat162*)(Cb + off) = hh;
                    __nv_bfloat162 ll;
                    ll.x = __float2bfloat16_rn(v0 - __bfloat162float(h0));
                    ll.y = __float2bfloat16_rn(v1 - __bfloat162float(h1));
                    *(__nv_bfloat162*)(Cb2 + off) = ll;
                }
            }
        }
    }
}

// ---------------------------------------------------------------------------
// tf32 single-term GEMM (round-6 config): BK=32, S=3, 512 threads, 128x128.
// A [M][K] fp32 row-major, B [N][K] fp32, values pre-rounded tf32.
// EPI: 0 plain; 1 tf32-rounded.
// ---------------------------------------------------------------------------
template<int EPI>
__global__ void __launch_bounds__(512)
gemm_cp(const float* __restrict__ A, const float* __restrict__ Bt,
        float* __restrict__ C,
        int K, int lda, int ldb, int ldc,
        long long azA, long long azB, long long azC) {
    constexpr int BK     = 32;
    constexpr int LDSR   = 36;
    constexpr int PLANE  = 128 * LDSR;
    constexpr int PLANEB = PLANE * 4;
    constexpr int S      = 3;
    constexpr int STAGEB = 2 * PLANEB;

    extern __shared__ char smc[];
    const uint32_t sbase = (uint32_t)__cvta_generic_to_shared(smc);

    const int tid  = threadIdx.x;
    const int warp = tid >> 5;
    const int lane = tid & 31;
    const int wm   = (warp >> 2) * 32;
    const int wn   = (warp & 3) * 32;
    const int grp  = lane >> 2;
    const int tig  = lane & 3;

    const int arow   = lane & 15;
    const int aoff16 = (lane >> 4) * 16;
    const int bsel   = (lane >> 4) & 1;
    const int boff16 = ((lane >> 3) & 1) * 16;
    const int brow   = lane & 7;

    const float* Ab = A  + (size_t)blockIdx.z * azA + (size_t)blockIdx.y * 128 * lda;
    const float* Bb = Bt + (size_t)blockIdx.z * azB + (size_t)blockIdx.x * 128 * ldb;

    float acc[2][4][4];
#pragma unroll
    for (int i = 0; i < 2; i++)
#pragma unroll
        for (int j = 0; j < 4; j++)
#pragma unroll
            for (int r = 0; r < 4; r++) acc[i][j][r] = 0.f;

    auto issue = [&](int kt) {
        const int k0 = kt * BK;
        const uint32_t sa = sbase + (uint32_t)((kt % S) * STAGEB);
#pragma unroll
        for (int i = 0; i < 2; i++) {
            int c = tid + i * 512;
            int m = c >> 3, kc = (c & 7) * 4;
            cp_async16(sa + (uint32_t)(m * LDSR + kc) * 4, Ab + (size_t)m * lda + k0 + kc);
        }
#pragma unroll
        for (int i = 0; i < 2; i++) {
            int c = tid + i * 512;
            int n = c >> 3, kc = (c & 7) * 4;
            cp_async16(sa + PLANEB + (uint32_t)(n * LDSR + kc) * 4, Bb + (size_t)n * ldb + k0 + kc);
        }
        cp_commit();
    };

    auto compute = [&](int kt) {
        const uint32_t stb   = sbase + (uint32_t)((kt % S) * STAGEB);
        const uint32_t a_hi0 = stb + (uint32_t)(wm + arow) * (LDSR * 4) + aoff16;
        const uint32_t b_hi0 = stb + PLANEB + (uint32_t)(wn + bsel * 8 + brow) * (LDSR * 4) + boff16;
#pragma unroll
        for (int ks = 0; ks < BK / 8; ks++) {
            const uint32_t kb = ks * 32;
            uint32_t ah[2][4], bh[2][4];
#pragma unroll
            for (int mi = 0; mi < 2; mi++)
                ldsm4(ah[mi][0], ah[mi][1], ah[mi][2], ah[mi][3],
                      a_hi0 + mi * (16 * LDSR * 4) + kb);
#pragma unroll
            for (int p = 0; p < 2; p++)
                ldsm4(bh[p][0], bh[p][1], bh[p][2], bh[p][3],
                      b_hi0 + p * (16 * LDSR * 4) + kb);
#pragma unroll
            for (int mi = 0; mi < 2; mi++)
#pragma unroll
                for (int ni = 0; ni < 4; ni++) {
                    const int p = ni >> 1, q = (ni & 1) * 2;
                    mma_tf32(acc[mi][ni][0], acc[mi][ni][1], acc[mi][ni][2], acc[mi][ni][3],
                             ah[mi][0], ah[mi][1], ah[mi][2], ah[mi][3],
                             bh[p][q], bh[p][q + 1]);
                }
        }
    };

    const int KT = K / BK;
    for (int i = 0; i < S; i++) {
        if (i < KT) issue(i); else cp_commit();
    }
    for (int kt = 0; kt < KT; kt++) {
        cp_wait<S - 1>();
        __syncthreads();
        compute(kt);
        __syncthreads();
        if (kt + S < KT) issue(kt + S); else cp_commit();
    }

    C += (size_t)blockIdx.z * azC;
#pragma unroll
    for (int mi = 0; mi < 2; mi++) {
        int m0 = blockIdx.y * 128 + wm + mi * 16 + grp;
#pragma unroll
        for (int ni = 0; ni < 4; ni++) {
            int n = blockIdx.x * 128 + wn + ni * 8 + tig * 2;
#pragma unroll
            for (int half = 0; half < 2; half++) {
                size_t off = (size_t)(m0 + half * 8) * ldc + n;
                float v0 = acc[mi][ni][half * 2], v1 = acc[mi][ni][half * 2 + 1];
                if (EPI == 0) *(float2*)(C + off) = make_float2(v0, v1);
                else          *(float2*)(C + off) = make_float2(tf32r(v0), tf32r(v1));
            }
        }
    }
}

// ---------------------------------------------------------------------------
__global__ void split_bf16_kernel(const float* __restrict__ in,
                                  __nv_bfloat16* __restrict__ bh,
                                  __nv_bfloat16* __restrict__ bl, int n) {
    int i = blockIdx.x * blockDim.x + threadIdx.x;
    if (i >= n) return;
    float v = in[i];
    __nv_bfloat16 h = __float2bfloat16_rn(v);
    bh[i] = h;
    bl[i] = __float2bfloat16_rn(v - __bfloat162float(h));
}

// in[K][N] fp32 -> outHi/outLo [N][K] bf16
__global__ void transpose_bf16(const float* __restrict__ in,
                               __nv_bfloat16* __restrict__ outHi,
                               __nv_bfloat16* __restrict__ outLo,
                               int K, int N) {
    __shared__ float tile[32][33];
    int n0 = blockIdx.x * 32, k0 = blockIdx.y * 32;
#pragma unroll
    for (int i = threadIdx.y; i < 32; i += 8)
        tile[i][threadIdx.x] = in[(size_t)(k0 + i) * N + n0 + threadIdx.x];
    __syncthreads();
#pragma unroll
    for (int i = threadIdx.y; i < 32; i += 8) {
        float v = tile[threadIdx.x][i];
        size_t off = (size_t)(n0 + i) * K + k0 + threadIdx.x;
        __nv_bfloat16 h = __float2bfloat16_rn(v);
        outHi[off] = h;
        outLo[off] = __float2bfloat16_rn(v - __bfloat162float(h));
    }
}

// in[K][N] fp32 -> out [N][K] fp32 tf32-rounded (batched)
__global__ void transpose_round(const float* __restrict__ in, float* __restrict__ outF,
                                int K, int N, long long inBatch, long long outBatch) {
    __shared__ float tile[32][33];
    const float* inb = in + (size_t)blockIdx.z * inBatch;
    float* oh = outF + (size_t)blockIdx.z * outBatch;
    int n0 = blockIdx.x * 32, k0 = blockIdx.y * 32;
#pragma unroll
    for (int i = threadIdx.y; i < 32; i += 8)
        tile[i][threadIdx.x] = inb[(size_t)(k0 + i) * N + n0 + threadIdx.x];
    __syncthreads();
#pragma unroll
    for (int i = threadIdx.y; i < 32; i += 8)
        oh[(size_t)(n0 + i) * K + k0 + threadIdx.x] = tf32r(tile[threadIdx.x][i]);
}

// ---------------------------------------------------------------------------
__global__ void rope_norm_kernel(float* __restrict__ x, const float* __restrict__ w,
                                 int nrows, int heads, int stride) {
    int gid  = blockIdx.x * blockDim.x + threadIdx.x;
    int wid  = gid >> 5;
    int lane = threadIdx.x & 31;
    if (wid >= nrows) return;
    int pos = (wid / heads) % C_T;

    float* row = x + (size_t)wid * stride;
    float a  = row[lane];
    float b2 = row[lane + 32];
    float c  = row[lane + 64];
    float e  = row[lane + 96];

    double invd = exp(-log(10000.0) * (double)(2 * lane) / 64.0);
    double ang  = (double)pos * invd;
    float cs = (float)cos(ang);
    float sn = (float)sin(ang);

    float r1 = a * cs - b2 * sn;
    float r2 = a * sn + b2 * cs;

    float ss = r1 * r1 + r2 * r2 + c * c + e * e;
#pragma unroll
    for (int off = 16; off; off >>= 1) ss += __shfl_xor_sync(0xffffffffu, ss, off);
    float rms = rsqrtf(ss * (1.0f / 128.0f) + 1e-6f);

    row[lane]      = r1 * rms * w[lane];
    row[lane + 32] = r2 * rms * w[lane + 32];
    row[lane + 64] = c  * rms * w[lane + 64];
    row[lane + 96] = e  * rms * w[lane + 96];
}

// ---------------------------------------------------------------------------
// Attention: block per (t, b); 16 warps = 16 heads. 4 keys per warp-iteration:
// lane groups of 8 each own one key's dot (16 dims/lane), 3-level reduce.
// K/V staged in smem chunks of 32 keys, row stride padded to 264 floats.
// ---------------------------------------------------------------------------
constexpr int KVS = 264;   // smem row stride in floats (1056B: 8-bank shift/row)

__global__ void __launch_bounds__(512)
attn_kernel(const float* __restrict__ q, const float* __restrict__ kv,
            const float* __restrict__ sink, float* __restrict__ att) {
    __shared__ float skv[32 * KVS];

    int t = blockIdx.x, b = blockIdx.y;
    int h    = threadIdx.x >> 5;
    int lane = threadIdx.x & 31;
    int tid  = threadIdx.x;
    int g    = lane >> 3;        // key group 0..3
    int r    = lane & 7;         // lane within group
    int token = b * C_T + t;

    // zero buffer once (masked keys in first chunk read finite zeros)
    {
        float4* s4 = (float4*)skv;
        for (int i = tid; i < 32 * (KVS / 4); i += 512)
            s4[i] = make_float4(0.f, 0.f, 0.f, 0.f);
    }

    const float scale = 0.08838834764831845f;   // 1/sqrt(128)
    // Q: this lane handles dims 16r..16r+15 (4 float4), pre-scaled
    const float4* q4p = (const float4*)(q + (size_t)token * (C_H * C_D) + h * C_D);
    float4 qr[4];
#pragma unroll
    for (int i = 0; i < 4; i++) {
        float4 v = q4p[r * 4 + i];
        qr[i] = make_float4(v.x * scale, v.y * scale, v.z * scale, v.w * scale);
    }

    float m = -1e30f, ssum = 0.f;
    float4 av = make_float4(0.f, 0.f, 0.f, 0.f);

    int s0 = t - (C_WIN - 1);
    if (s0 < 0) s0 = 0;

    for (int c0 = s0; c0 <= t; c0 += 32) {
        int cnt = t - c0 + 1;
        if (cnt > 32) cnt = 32;
        __syncthreads();
        const float4* src = (const float4*)(kv + (size_t)(b * C_T + c0) * (2 * C_D));
        for (int i = tid; i < cnt * 64; i += 512) {
            int row = i >> 6, c = i & 63;
            ((float4*)skv)[row * (KVS / 4) + c] = src[i];
        }
        __syncthreads();

        for (int j0 = 0; j0 < cnt; j0 += 4) {
            int kj = j0 + g;
            const float4* kr = (const float4*)(skv + kj * KVS + r * 16);
            float d = 0.f;
#pragma unroll
            for (int i = 0; i < 4; i++) {
                float4 kx = kr[i];
                d += qr[i].x * kx.x + qr[i].y * kx.y + qr[i].z * kx.z + qr[i].w * kx.w;
            }
            d += __shfl_xor_sync(0xffffffffu, d, 1);
            d += __shfl_xor_sync(0xffffffffu, d, 2);
            d += __shfl_xor_sync(0xffffffffu, d, 4);
            if (kj >= cnt) d = -1e30f;

            float d0 = __shfl_sync(0xffffffffu, d, r);
            float d1 = __shfl_sync(0xffffffffu, d, 8 + r);
            float d2 = __shfl_sync(0xffffffffu, d, 16 + r);
            float d3 = __shfl_sync(0xffffffffu, d, 24 + r);

            float mloc = fmaxf(fmaxf(d0, d1), fmaxf(d2, d3));
            float mn   = fmaxf(m, mloc);
            float corr = __expf(m - mn);
            float p0 = __expf(d0 - mn);
            float p1 = __expf(d1 - mn);
            float p2 = __expf(d2 - mn);
            float p3 = __expf(d3 - mn);
            ssum = ssum * corr + (p0 + p1 + p2 + p3);

            const float* vb = skv + 128 + lane * 4;
            float4 v0 = *(const float4*)(vb + (j0 + 0) * KVS);
            float4 v1 = *(const float4*)(vb + (j0 + 1) * KVS);
            float4 v2 = *(const float4*)(vb + (j0 + 2) * KVS);
            float4 v3 = *(const float4*)(vb + (j0 + 3) * KVS);
            av.x = av.x * corr + p0 * v0.x + p1 * v1.x + p2 * v2.x + p3 * v3.x;
            av.y = av.y * corr + p0 * v0.y + p1 * v1.y + p2 * v2.y + p3 * v3.y;
            av.z = av.z * corr + p0 * v0.z + p1 * v1.z + p2 * v2.z + p3 * v3.z;
            av.w = av.w * corr + p0 * v0.w + p1 * v1.w + p2 * v2.w + p3 * v3.w;
            m = mn;
        }
    }

    float sl   = sink[h];
    float mn   = fmaxf(m, sl);
    float corr = __expf(m - mn);
    ssum = ssum * corr + __expf(sl - mn);
    float inv = corr / ssum;

    float4* orow = (float4*)(att + (size_t)token * (C_H * C_D) + h * C_D);
    orow[lane] = make_float4(tf32r(av.x * inv), tf32r(av.y * inv),
                             tf32r(av.z * inv), tf32r(av.w * inv));
}

// ---------------------------------------------------------------------------
extern "C" void kernel_launch(void* const* d_in, const int* in_sizes, int n_in,
                              void* d_out, int out_size) {
    const float* h_in     = (const float*)d_in[0];
    const float* wq_comp  = (const float*)d_in[1];
    const float* wq_up    = (const float*)d_in[2];
    const float* wk       = (const float*)d_in[3];
    const float* wv       = (const float*)d_in[4];
    const float* q_norm_w = (const float*)d_in[5];
    const float* k_norm_w = (const float*)d_in[6];
    const float* sink     = (const float*)d_in[7];
    const float* out_w1   = (const float*)d_in[8];
    const float* out_w2   = (const float*)d_in[9];
    float* out = (float*)d_out;

    __nv_bfloat16 *hbh, *hbl, *hcbh, *hcbl, *wqcBh, *wqcBl, *wquBh, *wquBl, *wkvBh, *wkvBl;
    float *q, *kv, *att, *y1, *w1T, *w2T;
    cudaGetSymbolAddress((void**)&hbh,  g_h_bh);
    cudaGetSymbolAddress((void**)&hbl,  g_h_bl);
    cudaGetSymbolAddress((void**)&hcbh, g_hc_bh);
    cudaGetSymbolAddress((void**)&hcbl, g_hc_bl);
    cudaGetSymbolAddress((void**)&q,    g_q);
    cudaGetSymbolAddress((void**)&kv,   g_kv);
    cudaGetSymbolAddress((void**)&att,  g_att);
    cudaGetSymbolAddress((void**)&y1,   g_y1);
    cudaGetSymbolAddress((void**)&wqcBh, g_wqcT_bh);
    cudaGetSymbolAddress((void**)&wqcBl, g_wqcT_bl);
    cudaGetSymbolAddress((void**)&wquBh, g_wquT_bh);
    cudaGetSymbolAddress((void**)&wquBl, g_wquT_bl);
    cudaGetSymbolAddress((void**)&wkvBh, g_wkvT_bh);
    cudaGetSymbolAddress((void**)&wkvBl, g_wkvT_bl);
    cudaGetSymbolAddress((void**)&w1T,  g_w1T);
    cudaGetSymbolAddress((void**)&w2T,  g_w2T);

    // smem sizes
    constexpr int BF_STG_128 = 2 * (128 * 144 + 128 * 144);   // 73728
    constexpr int BF_STG_64  = 2 * (64 * 144 + 128 * 144);    // 55296
    constexpr int SM_BF_128  = 2 * BF_STG_128;                // 147456
    constexpr int SM_BF_64   = 2 * BF_STG_64;                 // 110592
    constexpr int SM_TF      = 3 * 2 * 128 * 36 * 4;          // 110592
    cudaFuncSetAttribute(gemm_bf16<3,64>,  cudaFuncAttributeMaxDynamicSharedMemorySize, SM_BF_64);
    cudaFuncSetAttribute(gemm_bf16<0,64>,  cudaFuncAttributeMaxDynamicSharedMemorySize, SM_BF_64);
    cudaFuncSetAttribute(gemm_bf16<0,128>, cudaFuncAttributeMaxDynamicSharedMemorySize, SM_BF_128);
    cudaFuncSetAttribute(gemm_cp<1>, cudaFuncAttributeMaxDynamicSharedMemorySize, SM_TF);
    cudaFuncSetAttribute(gemm_cp<0>, cudaFuncAttributeMaxDynamicSharedMemorySize, SM_TF);

    dim3 tb(32, 8);

    // --- packing ---
    split_bf16_kernel<<<(C_TOK * C_HID + 255) / 256, 256>>>(h_in, hbh, hbl, C_TOK * C_HID);
    transpose_bf16<<<dim3(C_QC/32, C_HID/32), tb>>>(wq_comp, wqcBh, wqcBl, C_HID, C_QC);
    transpose_bf16<<<dim3(C_H*C_D/32, C_QC/32), tb>>>(wq_up, wquBh, wquBl, C_QC, C_H*C_D);
    transpose_bf16<<<dim3(C_D/32, C_HID/32), tb>>>(wk, wkvBh, wkvBl, C_HID, C_D);
    transpose_bf16<<<dim3(C_D/32, C_HID/32), tb>>>(wv, wkvBh + (size_t)C_D*C_HID,
                                                   wkvBl + (size_t)C_D*C_HID, C_HID, C_D);
    transpose_round<<<dim3(C_INTER/32, (C_H/C_G)*C_D/32, C_G), tb>>>(
        out_w1, w1T, (C_H/C_G)*C_D, C_INTER,
        (long long)(C_H/C_G)*C_D*C_INTER, (long long)C_INTER*(C_H/C_G)*C_D);
    transpose_round<<<dim3(C_HID/32, C_G*C_INTER/32, 1), tb>>>(
        out_w2, w2T, C_G*C_INTER, C_HID, 0, 0);

    // --- 1) hc = h @ wq_comp (bf16 3-term, BM=64, bf16 hi/lo out) ---
    gemm_bf16<3,64><<<dim3(C_QC/128, C_TOK/64), 256, SM_BF_64>>>(
        hbh, hbl, wqcBh, wqcBl, nullptr, hcbh, hcbl,
        C_HID, C_HID, C_HID, C_QC);

    // --- 2) q = hc @ wq_up (bf16 3-term, BM=128, fp32 out) ---
    gemm_bf16<0,128><<<dim3(C_H*C_D/128, C_TOK/128), 512, SM_BF_128>>>(
        hcbh, hcbl, wquBh, wquBl, q, nullptr, nullptr,
        C_QC, C_QC, C_QC, C_H*C_D);

    // --- 3) kv = h @ wkv (bf16 3-term, BM=64, fp32 out) ---
    gemm_bf16<0,64><<<dim3(2*C_D/128, C_TOK/64), 256, SM_BF_64>>>(
        hbh, hbl, wkvBh, wkvBl, kv, nullptr, nullptr,
        C_HID, C_HID, C_HID, 2*C_D);

    // --- 4) RoPE + RMSNorm ---
    {
        int rows = C_TOK * C_H;
        rope_norm_kernel<<<(rows * 32 + 255) / 256, 256>>>(q, q_norm_w, rows, C_H, C_D);
    }
    {
        int rows = C_TOK;
        rope_norm_kernel<<<(rows * 32 + 255) / 256, 256>>>(kv, k_norm_w, rows, 1, 2*C_D);
    }

    // --- 5) attention (tf32-rounded output) ---
    attn_kernel<<<dim3(C_T, C_B), 512>>>(q, kv, sink, att);

    // --- 6) y1 = grouped att @ w1 (tf32 single, z-batched, rounded out) ---
    gemm_cp<1><<<dim3(C_INTER/128, C_TOK/128, C_G), 512, SM_TF>>>(
        att, w1T, y1,
        (C_H/C_G)*C_D, C_H*C_D, (C_H/C_G)*C_D, C_G*C_INTER,
        (long long)(C_H/C_G)*C_D,
        (long long)C_INTER*(C_H/C_G)*C_D,
        (long long)C_INTER);

    // --- 7) out = y1 @ out_w2 (tf32 single) ---
    gemm_cp<0><<<dim3(C_HID/128, C_TOK/128, 1), 512, SM_TF>>>(
        y1, w2T, out,
        C_G*C_INTER, C_G*C_INTER, C_G*C_INTER, C_HID, 0, 0, 0);
}

// round 9
// speedup vs baseline: 1.2713x; 1.2713x over previous
#include <cuda_runtime.h>
#include <math.h>
#include <stdint.h>

// Problem constants
constexpr int C_B    = 2;
constexpr int C_T    = 2048;
constexpr int C_HID  = 2048;
constexpr int C_H    = 16;
constexpr int C_D    = 128;
constexpr int C_WIN  = 512;
constexpr int C_QC   = 512;
constexpr int C_G    = 4;
constexpr int C_INTER= 2048;
constexpr int C_TOK  = C_B * C_T;

// ---------------------------------------------------------------------------
// Scratch (device globals) — all fp32, values tf32-exact where GEMM inputs
// ---------------------------------------------------------------------------
__device__ float g_h  [C_TOK * C_HID];
__device__ float g_hc [C_TOK * C_QC];
__device__ float g_q  [C_TOK * C_H * C_D];
__device__ float g_kv [C_TOK * 2 * C_D];
__device__ float g_att[C_TOK * C_H * C_D];
__device__ float g_y1 [C_TOK * C_G * C_INTER];
__device__ float g_wqcT[C_QC * C_HID];
__device__ float g_wquT[C_H * C_D * C_QC];
__device__ float g_wkvT[2 * C_D * C_HID];
__device__ float g_w1T [C_G * C_INTER * (C_H / C_G) * C_D];
__device__ float g_w2T [C_HID * C_G * C_INTER];

__device__ __forceinline__ uint32_t f2tf32(float f) {
    uint32_t r;
    asm("cvt.rna.tf32.f32 %0, %1;" : "=r"(r) : "f"(f));
    return r;
}
__device__ __forceinline__ float tf32r(float f) { return __uint_as_float(f2tf32(f)); }

__device__ __forceinline__ void mma_tf32(float& c0, float& c1, float& c2, float& c3,
                                         uint32_t a0, uint32_t a1, uint32_t a2, uint32_t a3,
                                         uint32_t b0, uint32_t b1) {
    asm volatile(
        "mma.sync.aligned.m16n8k8.row.col.f32.tf32.tf32.f32 "
        "{%0,%1,%2,%3}, {%4,%5,%6,%7}, {%8,%9}, {%0,%1,%2,%3};"
        : "+f"(c0), "+f"(c1), "+f"(c2), "+f"(c3)
        : "r"(a0), "r"(a1), "r"(a2), "r"(a3), "r"(b0), "r"(b1));
}

__device__ __forceinline__ void ldsm4(uint32_t& r0, uint32_t& r1, uint32_t& r2, uint32_t& r3,
                                      uint32_t addr) {
    asm volatile("ldmatrix.sync.aligned.m8n8.x4.shared.b16 {%0,%1,%2,%3}, [%4];"
                 : "=r"(r0), "=r"(r1), "=r"(r2), "=r"(r3) : "r"(addr));
}

__device__ __forceinline__ void cp_async16(uint32_t saddr, const void* g) {
    asm volatile("cp.async.cg.shared.global [%0], [%1], 16;\n" :: "r"(saddr), "l"(g));
}
__device__ __forceinline__ void cp_commit() { asm volatile("cp.async.commit_group;\n"); }
template<int N>
__device__ __forceinline__ void cp_wait() { asm volatile("cp.async.wait_group %0;\n" :: "n"(N)); }

// ---------------------------------------------------------------------------
// tf32 single-term GEMM (R6 config): BK=32, S=3 stages, 512 threads, 128x128.
// A [M][K] fp32 row-major, B [N][K] fp32 (k-contiguous), values tf32-exact.
// EPI: 0 plain fp32 C; 1 tf32-rounded C.
// ---------------------------------------------------------------------------
template<int EPI>
__global__ void __launch_bounds__(512)
gemm_cp(const float* __restrict__ A, const float* __restrict__ Bt,
        float* __restrict__ C,
        int K, int lda, int ldb, int ldc,
        long long azA, long long azB, long long azC) {
    constexpr int BK     = 32;
    constexpr int LDSR   = 36;
    constexpr int PLANE  = 128 * LDSR;
    constexpr int PLANEB = PLANE * 4;
    constexpr int S      = 3;
    constexpr int STAGEB = 2 * PLANEB;

    extern __shared__ char smc[];
    const uint32_t sbase = (uint32_t)__cvta_generic_to_shared(smc);

    const int tid  = threadIdx.x;
    const int warp = tid >> 5;
    const int lane = tid & 31;
    const int wm   = (warp >> 2) * 32;
    const int wn   = (warp & 3) * 32;
    const int grp  = lane >> 2;
    const int tig  = lane & 3;

    const int arow   = lane & 15;
    const int aoff16 = (lane >> 4) * 16;
    const int bsel   = (lane >> 4) & 1;
    const int boff16 = ((lane >> 3) & 1) * 16;
    const int brow   = lane & 7;

    const float* Ab = A  + (size_t)blockIdx.z * azA + (size_t)blockIdx.y * 128 * lda;
    const float* Bb = Bt + (size_t)blockIdx.z * azB + (size_t)blockIdx.x * 128 * ldb;

    float acc[2][4][4];
#pragma unroll
    for (int i = 0; i < 2; i++)
#pragma unroll
        for (int j = 0; j < 4; j++)
#pragma unroll
            for (int r = 0; r < 4; r++) acc[i][j][r] = 0.f;

    auto issue = [&](int kt) {
        const int k0 = kt * BK;
        const uint32_t sa = sbase + (uint32_t)((kt % S) * STAGEB);
#pragma unroll
        for (int i = 0; i < 2; i++) {
            int c = tid + i * 512;
            int m = c >> 3, kc = (c & 7) * 4;
            cp_async16(sa + (uint32_t)(m * LDSR + kc) * 4, Ab + (size_t)m * lda + k0 + kc);
        }
#pragma unroll
        for (int i = 0; i < 2; i++) {
            int c = tid + i * 512;
            int n = c >> 3, kc = (c & 7) * 4;
            cp_async16(sa + PLANEB + (uint32_t)(n * LDSR + kc) * 4, Bb + (size_t)n * ldb + k0 + kc);
        }
        cp_commit();
    };

    auto compute = [&](int kt) {
        const uint32_t stb   = sbase + (uint32_t)((kt % S) * STAGEB);
        const uint32_t a_hi0 = stb + (uint32_t)(wm + arow) * (LDSR * 4) + aoff16;
        const uint32_t b_hi0 = stb + PLANEB + (uint32_t)(wn + bsel * 8 + brow) * (LDSR * 4) + boff16;
#pragma unroll
        for (int ks = 0; ks < BK / 8; ks++) {
            const uint32_t kb = ks * 32;
            uint32_t ah[2][4], bh[2][4];
#pragma unroll
            for (int mi = 0; mi < 2; mi++)
                ldsm4(ah[mi][0], ah[mi][1], ah[mi][2], ah[mi][3],
                      a_hi0 + mi * (16 * LDSR * 4) + kb);
#pragma unroll
            for (int p = 0; p < 2; p++)
                ldsm4(bh[p][0], bh[p][1], bh[p][2], bh[p][3],
                      b_hi0 + p * (16 * LDSR * 4) + kb);
#pragma unroll
            for (int mi = 0; mi < 2; mi++)
#pragma unroll
                for (int ni = 0; ni < 4; ni++) {
                    const int p = ni >> 1, q = (ni & 1) * 2;
                    mma_tf32(acc[mi][ni][0], acc[mi][ni][1], acc[mi][ni][2], acc[mi][ni][3],
                             ah[mi][0], ah[mi][1], ah[mi][2], ah[mi][3],
                             bh[p][q], bh[p][q + 1]);
                }
        }
    };

    const int KT = K / BK;
    for (int i = 0; i < S; i++) {
        if (i < KT) issue(i); else cp_commit();
    }
    for (int kt = 0; kt < KT; kt++) {
        cp_wait<S - 1>();
        __syncthreads();
        compute(kt);
        __syncthreads();
        if (kt + S < KT) issue(kt + S); else cp_commit();
    }

    C += (size_t)blockIdx.z * azC;
#pragma unroll
    for (int mi = 0; mi < 2; mi++) {
        int m0 = blockIdx.y * 128 + wm + mi * 16 + grp;
#pragma unroll
        for (int ni = 0; ni < 4; ni++) {
            int n = blockIdx.x * 128 + wn + ni * 8 + tig * 2;
#pragma unroll
            for (int half = 0; half < 2; half++) {
                size_t off = (size_t)(m0 + half * 8) * ldc + n;
                float v0 = acc[mi][ni][half * 2], v1 = acc[mi][ni][half * 2 + 1];
                if (EPI == 0) *(float2*)(C + off) = make_float2(v0, v1);
                else          *(float2*)(C + off) = make_float2(tf32r(v0), tf32r(v1));
            }
        }
    }
}

// ---------------------------------------------------------------------------
// Pack megakernel: region 0 rounds h; regions 1..6 transpose+round weights.
// 256 threads/block.
// ---------------------------------------------------------------------------
constexpr int PB_H   = 4096;    // h round: 2048 floats per block
constexpr int PB_WQC = 1024;    // (512/32)*(2048/32)
constexpr int PB_WQU = 1024;
constexpr int PB_WK  = 256;
constexpr int PB_WV  = 256;
constexpr int PB_W1  = 4096;    // 1024 * 4 groups
constexpr int PB_W2  = 16384;
constexpr int PB_TOTAL = PB_H + PB_WQC + PB_WQU + PB_WK + PB_WV + PB_W1 + PB_W2;

__device__ __forceinline__ void pk_transpose(const float* __restrict__ src,
                                             float* __restrict__ dst,
                                             int K, int N, int tile) {
    __shared__ float t[32][33];
    int tx = threadIdx.x & 31, ty = threadIdx.x >> 5;
    int ntx = N / 32;
    int n0 = (tile % ntx) * 32, k0 = (tile / ntx) * 32;
#pragma unroll
    for (int i = ty; i < 32; i += 8)
        t[i][tx] = src[(size_t)(k0 + i) * N + n0 + tx];
    __syncthreads();
#pragma unroll
    for (int i = ty; i < 32; i += 8)
        dst[(size_t)(n0 + i) * K + k0 + tx] = tf32r(t[tx][i]);
}

__global__ void __launch_bounds__(256)
pack_kernel(const float* __restrict__ h_in, float* __restrict__ h_r,
            const float* __restrict__ wqc, float* __restrict__ wqcT,
            const float* __restrict__ wqu, float* __restrict__ wquT,
            const float* __restrict__ wk,  const float* __restrict__ wv,
            float* __restrict__ wkvT,
            const float* __restrict__ w1,  float* __restrict__ w1T,
            const float* __restrict__ w2,  float* __restrict__ w2T) {
    int b = blockIdx.x;
    if (b < PB_H) {
        size_t base = (size_t)b * 2048 + threadIdx.x * 8;
#pragma unroll
        for (int i = 0; i < 2; i++) {
            float4 v = *(const float4*)(h_in + base + i * 4);
            *(float4*)(h_r + base + i * 4) =
                make_float4(tf32r(v.x), tf32r(v.y), tf32r(v.z), tf32r(v.w));
        }
        return;
    }
    b -= PB_H;
    if (b < PB_WQC) { pk_transpose(wqc, wqcT, C_HID, C_QC, b); return; }
    b -= PB_WQC;
    if (b < PB_WQU) { pk_transpose(wqu, wquT, C_QC, C_H * C_D, b); return; }
    b -= PB_WQU;
    if (b < PB_WK)  { pk_transpose(wk, wkvT, C_HID, C_D, b); return; }
    b -= PB_WK;
    if (b < PB_WV)  { pk_transpose(wv, wkvT + (size_t)C_D * C_HID, C_HID, C_D, b); return; }
    b -= PB_WV;
    if (b < PB_W1) {
        int g = b / 1024, tile = b % 1024;
        pk_transpose(w1 + (size_t)g * (C_H / C_G) * C_D * C_INTER,
                     w1T + (size_t)g * C_INTER * (C_H / C_G) * C_D,
                     (C_H / C_G) * C_D, C_INTER, tile);
        return;
    }
    b -= PB_W1;
    pk_transpose(w2, w2T, C_G * C_INTER, C_HID, b);
}

// ---------------------------------------------------------------------------
// Combined RoPE + RMSNorm for q and k. One warp per row.
// ---------------------------------------------------------------------------
__global__ void __launch_bounds__(256)
rope_kernel(float* __restrict__ q, float* __restrict__ kv,
            const float* __restrict__ qw, const float* __restrict__ kw) {
    int gid  = blockIdx.x * blockDim.x + threadIdx.x;
    int wid  = gid >> 5;
    int lane = threadIdx.x & 31;

    float* row;
    const float* w;
    int pos;
    if (wid < C_TOK * C_H) {
        row = q + (size_t)wid * C_D;
        w = qw;
        pos = (wid / C_H) % C_T;
    } else {
        int wk2 = wid - C_TOK * C_H;
        if (wk2 >= C_TOK) return;
        row = kv + (size_t)wk2 * (2 * C_D);
        w = kw;
        pos = wk2 % C_T;
    }

    float a  = row[lane];
    float b2 = row[lane + 32];
    float c  = row[lane + 64];
    float e  = row[lane + 96];

    double invd = exp(-log(10000.0) * (double)(2 * lane) / 64.0);
    double ang  = (double)pos * invd;
    float cs = (float)cos(ang);
    float sn = (float)sin(ang);

    float r1 = a * cs - b2 * sn;
    float r2 = a * sn + b2 * cs;

    float ss = r1 * r1 + r2 * r2 + c * c + e * e;
#pragma unroll
    for (int off = 16; off; off >>= 1) ss += __shfl_xor_sync(0xffffffffu, ss, off);
    float rms = rsqrtf(ss * (1.0f / 128.0f) + 1e-6f);

    row[lane]      = r1 * rms * w[lane];
    row[lane + 32] = r2 * rms * w[lane + 32];
    row[lane + 64] = c  * rms * w[lane + 64];
    row[lane + 96] = e  * rms * w[lane + 96];
}

// ---------------------------------------------------------------------------
// Attention (R6 version): block per (t, b); 16 warps = 16 heads; K/V staged
// through smem in chunks of 32 keys shared by all heads.
// ---------------------------------------------------------------------------
__global__ void __launch_bounds__(512)
attn_kernel(const float* __restrict__ q, const float* __restrict__ kv,
            const float* __restrict__ sink, float* __restrict__ att) {
    __shared__ float skv[32 * 2 * C_D];

    int t = blockIdx.x, b = blockIdx.y;
    int h    = threadIdx.x >> 5;
    int lane = threadIdx.x & 31;
    int tid  = threadIdx.x;
    int token = b * C_T + t;

    const float4* q4p = (const float4*)(q + (size_t)token * (C_H * C_D) + h * C_D);
    float4 qv = q4p[lane];

    const float scale = 0.08838834764831845f;
    float m = -1e30f, ssum = 0.f;
    float4 av = make_float4(0.f, 0.f, 0.f, 0.f);

    int s0 = t - (C_WIN - 1);
    if (s0 < 0) s0 = 0;

    for (int c0 = s0; c0 <= t; c0 += 32) {
        int cnt = t - c0 + 1;
        if (cnt > 32) cnt = 32;
        __syncthreads();
        const float4* src = (const float4*)(kv + (size_t)(b * C_T + c0) * (2 * C_D));
        for (int i = tid; i < cnt * 64; i += 512)
            ((float4*)skv)[i] = src[i];
        __syncthreads();

        for (int j = 0; j < cnt; j++) {
            const float4* krow = (const float4*)(skv + j * (2 * C_D));
            float4 kvec = krow[lane];
            float d = qv.x * kvec.x + qv.y * kvec.y + qv.z * kvec.z + qv.w * kvec.w;
#pragma unroll
            for (int off = 16; off; off >>= 1) d += __shfl_xor_sync(0xffffffffu, d, off);
            d *= scale;

            float mn   = fmaxf(m, d);
            float corr = __expf(m - mn);
            float p    = __expf(d - mn);

            float4 vvec = krow[32 + lane];
            ssum = ssum * corr + p;
            av.x = av.x * corr + p * vvec.x;
            av.y = av.y * corr + p * vvec.y;
            av.z = av.z * corr + p * vvec.z;
            av.w = av.w * corr + p * vvec.w;
            m = mn;
        }
    }

    float sl   = sink[h];
    float mn   = fmaxf(m, sl);
    float corr = __expf(m - mn);
    ssum = ssum * corr + __expf(sl - mn);
    float inv = corr / ssum;

    float4* orow = (float4*)(att + (size_t)token * (C_H * C_D) + h * C_D);
    orow[lane] = make_float4(tf32r(av.x * inv), tf32r(av.y * inv),
                             tf32r(av.z * inv), tf32r(av.w * inv));
}

// ---------------------------------------------------------------------------
extern "C" void kernel_launch(void* const* d_in, const int* in_sizes, int n_in,
                              void* d_out, int out_size) {
    const float* h_in     = (const float*)d_in[0];
    const float* wq_comp  = (const float*)d_in[1];
    const float* wq_up    = (const float*)d_in[2];
    const float* wk       = (const float*)d_in[3];
    const float* wv       = (const float*)d_in[4];
    const float* q_norm_w = (const float*)d_in[5];
    const float* k_norm_w = (const float*)d_in[6];
    const float* sink     = (const float*)d_in[7];
    const float* out_w1   = (const float*)d_in[8];
    const float* out_w2   = (const float*)d_in[9];
    float* out = (float*)d_out;

    float *h_r, *hc, *q, *kv, *att, *y1, *wqcT, *wquT, *wkvT, *w1T, *w2T;
    cudaGetSymbolAddress((void**)&h_r,  g_h);
    cudaGetSymbolAddress((void**)&hc,   g_hc);
    cudaGetSymbolAddress((void**)&q,    g_q);
    cudaGetSymbolAddress((void**)&kv,   g_kv);
    cudaGetSymbolAddress((void**)&att,  g_att);
    cudaGetSymbolAddress((void**)&y1,   g_y1);
    cudaGetSymbolAddress((void**)&wqcT, g_wqcT);
    cudaGetSymbolAddress((void**)&wquT, g_wquT);
    cudaGetSymbolAddress((void**)&wkvT, g_wkvT);
    cudaGetSymbolAddress((void**)&w1T,  g_w1T);
    cudaGetSymbolAddress((void**)&w2T,  g_w2T);

    constexpr int SM_TF = 3 * 2 * 128 * 36 * 4;   // 110592 B
    cudaFuncSetAttribute(gemm_cp<1>, cudaFuncAttributeMaxDynamicSharedMemorySize, SM_TF);
    cudaFuncSetAttribute(gemm_cp<0>, cudaFuncAttributeMaxDynamicSharedMemorySize, SM_TF);

    // [0] pack: round h, transpose+round all weights
    pack_kernel<<<PB_TOTAL, 256>>>(h_in, h_r, wq_comp, wqcT, wq_up, wquT,
                                   wk, wv, wkvT, out_w1, w1T, out_w2, w2T);

    // [1] hc = h @ wq_comp (rounded out)
    gemm_cp<1><<<dim3(C_QC/128, C_TOK/128), 512, SM_TF>>>(
        h_r, wqcT, hc, C_HID, C_HID, C_HID, C_QC, 0, 0, 0);

    // [2] q = hc @ wq_up
    gemm_cp<0><<<dim3(C_H*C_D/128, C_TOK/128), 512, SM_TF>>>(
        hc, wquT, q, C_QC, C_QC, C_QC, C_H*C_D, 0, 0, 0);

    // [3] kv = h @ wkv
    gemm_cp<0><<<dim3(2*C_D/128, C_TOK/128), 512, SM_TF>>>(
        h_r, wkvT, kv, C_HID, C_HID, C_HID, 2*C_D, 0, 0, 0);

    // [4] RoPE + RMSNorm (q + k combined)
    {
        int warps = C_TOK * C_H + C_TOK;
        rope_kernel<<<(warps * 32 + 255) / 256, 256>>>(q, kv, q_norm_w, k_norm_w);
    }

    // [5] attention (profiled by ncu -s 5 -c 1)
    attn_kernel<<<dim3(C_T, C_B), 512>>>(q, kv, sink, att);

    // [6] y1 = grouped att @ w1 (z-batched, rounded out)
    gemm_cp<1><<<dim3(C_INTER/128, C_TOK/128, C_G), 512, SM_TF>>>(
        att, w1T, y1,
        (C_H/C_G)*C_D, C_H*C_D, (C_H/C_G)*C_D, C_G*C_INTER,
        (long long)(C_H/C_G)*C_D,
        (long long)C_INTER*(C_H/C_G)*C_D,
        (long long)C_INTER);

    // [7] out = y1 @ out_w2
    gemm_cp<0><<<dim3(C_HID/128, C_TOK/128), 512, SM_TF>>>(
        y1, w2T, out, C_G*C_INTER, C_G*C_INTER, C_G*C_INTER, C_HID, 0, 0, 0);
}

// round 10
// speedup vs baseline: 1.3856x; 1.0899x over previous
#include <cuda_runtime.h>
#include <math.h>
#include <stdint.h>

// Problem constants
constexpr int C_B    = 2;
constexpr int C_T    = 2048;
constexpr int C_HID  = 2048;
constexpr int C_H    = 16;
constexpr int C_D    = 128;
constexpr int C_WIN  = 512;
constexpr int C_QC   = 512;
constexpr int C_G    = 4;
constexpr int C_INTER= 2048;
constexpr int C_TOK  = C_B * C_T;
constexpr int TILE_F = 4096;            // floats per 16KB [128x32] tile

// ---------------------------------------------------------------------------
// Scratch (device globals). Tiled matrices: tile (rt, kt) of a [R][K] matrix
// lives at ((rt*KT + kt)*4096 + sw((r%128)*128 + (k%32)*4)/4), sw = SW128.
// ---------------------------------------------------------------------------
__device__ __align__(1024) float g_h_t  [(size_t)32 * 64  * TILE_F];  // h      [4096][2048]
__device__ __align__(1024) float g_hc_t [(size_t)32 * 16  * TILE_F];  // hc     [4096][512]
__device__ __align__(1024) float g_att_t[(size_t)32 * 64  * TILE_F];  // att    [4096][2048]
__device__ __align__(1024) float g_y1_t [(size_t)32 * 256 * TILE_F];  // y1     [4096][8192]
__device__ __align__(1024) float g_wqc_t[(size_t)4  * 64  * TILE_F];  // wqcT   [512][2048]
__device__ __align__(1024) float g_wqu_t[(size_t)16 * 16  * TILE_F];  // wquT   [2048][512]
__device__ __align__(1024) float g_wkv_t[(size_t)2  * 64  * TILE_F];  // wkvT   [256][2048]
__device__ __align__(1024) float g_w1_t [(size_t)4 * 16 * 16 * TILE_F]; // w1T per g [2048][512]
__device__ __align__(1024) float g_w2_t [(size_t)16 * 256 * TILE_F];  // w2T    [2048][8192]
__device__ float g_q [C_TOK * C_H * C_D];
__device__ float g_kv[C_TOK * 2 * C_D];

// ---------------------------------------------------------------------------
// Helpers
// ---------------------------------------------------------------------------
__device__ __forceinline__ uint32_t f2tf32(float f) {
    uint32_t r;
    asm("cvt.rna.tf32.f32 %0, %1;" : "=r"(r) : "f"(f));
    return r;
}
__device__ __forceinline__ float tf32r(float f) { return __uint_as_float(f2tf32(f)); }

__device__ __forceinline__ uint32_t sw128(uint32_t off) {
    return off ^ ((off >> 3) & 0x70);
}

__device__ __forceinline__ void mma_tf32(float& c0, float& c1, float& c2, float& c3,
                                         uint32_t a0, uint32_t a1, uint32_t a2, uint32_t a3,
                                         uint32_t b0, uint32_t b1) {
    asm volatile(
        "mma.sync.aligned.m16n8k8.row.col.f32.tf32.tf32.f32 "
        "{%0,%1,%2,%3}, {%4,%5,%6,%7}, {%8,%9}, {%0,%1,%2,%3};"
        : "+f"(c0), "+f"(c1), "+f"(c2), "+f"(c3)
        : "r"(a0), "r"(a1), "r"(a2), "r"(a3), "r"(b0), "r"(b1));
}

__device__ __forceinline__ void ldsm4(uint32_t& r0, uint32_t& r1, uint32_t& r2, uint32_t& r3,
                                      uint32_t addr) {
    asm volatile("ldmatrix.sync.aligned.m8n8.x4.shared.b16 {%0,%1,%2,%3}, [%4];"
                 : "=r"(r0), "=r"(r1), "=r"(r2), "=r"(r3) : "r"(addr));
}

__device__ __forceinline__ void mbar_init(uint32_t a, uint32_t cnt) {
    asm volatile("mbarrier.init.shared.b64 [%0], %1;" :: "r"(a), "r"(cnt) : "memory");
}
__device__ __forceinline__ void mbar_expect(uint32_t a, uint32_t bytes) {
    asm volatile("mbarrier.arrive.expect_tx.shared.b64 _, [%0], %1;"
                 :: "r"(a), "r"(bytes) : "memory");
}
__device__ __forceinline__ void mbar_wait(uint32_t a, uint32_t parity) {
    uint32_t done;
    asm volatile(
        "{\n\t.reg .pred p;\n\t"
        "mbarrier.try_wait.parity.acquire.cta.shared::cta.b64 p, [%1], %2;\n\t"
        "selp.b32 %0, 1, 0, p;\n\t}"
        : "=r"(done) : "r"(a), "r"(parity) : "memory");
    if (!done) {
        asm volatile(
            "{\n\t.reg .pred P1;\n\t"
            "WAIT_LOOP_%=:\n\t"
            "mbarrier.try_wait.parity.acquire.cta.shared::cta.b64 P1, [%0], %1, 0x989680;\n\t"
            "@P1 bra.uni WAIT_DONE_%=;\n\t"
            "bra.uni WAIT_LOOP_%=;\n\t"
            "WAIT_DONE_%=:\n\t}"
            :: "r"(a), "r"(parity) : "memory");
    }
}
__device__ __forceinline__ void bulk_g2s(uint32_t dst, const void* src, uint32_t bytes,
                                         uint32_t mbar) {
    asm volatile(
        "cp.async.bulk.shared::cta.global.mbarrier::complete_tx::bytes [%0], [%1], %2, [%3];"
        :: "r"(dst), "l"(src), "r"(bytes), "r"(mbar) : "memory");
}

// ---------------------------------------------------------------------------
// TMA-fed tf32 GEMM on tiled operands. 128x128 CTA tile, BK=32, 512 threads,
// 16 warps (4x4, warp tile 32x32). One thread issues 2 bulk copies per iter.
// A tiles at Abase + kt*TILE_F, B tiles at Bbase + kt*TILE_F.
// EPI 0: normal fp32 C (ldcP = ldc).  EPI 1: tiled + tf32-rounded C
// (ldcP = tiles per m-row, azC = C tile offset per blockIdx.z).
// ---------------------------------------------------------------------------
template<int EPI>
__global__ void __launch_bounds__(512)
gemm_tma(const float* __restrict__ A, const float* __restrict__ B, float* __restrict__ C,
         int KT, int ldaT, int ldbT, int azA, int azB, int ldcP, int azC) {
    constexpr int S = 4;
    constexpr int STAGEB = 2 * 16384;

    extern __shared__ __align__(16) char smc[];
    const uint32_t sbase = (uint32_t)__cvta_generic_to_shared(smc);
    const uint32_t mb0   = sbase;            // S mbarriers
    const uint32_t data0 = sbase + 1024;

    const int tid  = threadIdx.x;
    const int warp = tid >> 5;
    const int lane = tid & 31;
    const int wm   = (warp >> 2) * 32;
    const int wn   = (warp & 3) * 32;
    const int grp  = lane >> 2;
    const int tig  = lane & 3;

    const float* Abase = A + ((size_t)blockIdx.y * ldaT + (size_t)blockIdx.z * azA) * TILE_F;
    const float* Bbase = B + ((size_t)blockIdx.x * ldbT + (size_t)blockIdx.z * azB) * TILE_F;

    if (tid == 0) {
        for (int s = 0; s < S; s++) mbar_init(mb0 + 8 * s, 1);
    }
    __syncthreads();
    if (tid == 0) {
        for (int i = 0; i < S - 1 && i < KT; i++) {
            uint32_t mb = mb0 + 8 * i;
            mbar_expect(mb, 32768);
            bulk_g2s(data0 + i * STAGEB,         Abase + (size_t)i * TILE_F, 16384, mb);
            bulk_g2s(data0 + i * STAGEB + 16384, Bbase + (size_t)i * TILE_F, 16384, mb);
        }
    }

    float acc[2][4][4];
#pragma unroll
    for (int i = 0; i < 2; i++)
#pragma unroll
        for (int j = 0; j < 4; j++)
#pragma unroll
            for (int r = 0; r < 4; r++) acc[i][j][r] = 0.f;

    // ldmatrix per-lane addressing within swizzled [128x32] tile
    const int aRow = wm + (lane & 15);
    const uint32_t aOff = (uint32_t)((lane >> 4) * 16);
    const uint32_t aXor = (uint32_t)((aRow & 7) << 4);
    const uint32_t aB0  = (uint32_t)(aRow * 128);
    const int bRow = wn + ((lane >> 4) & 1) * 8 + (lane & 7);
    const uint32_t bOff = (uint32_t)(((lane >> 3) & 1) * 16);
    const uint32_t bXor = (uint32_t)((lane & 7) << 4);        // bRow&7 == lane&7
    const uint32_t bB0  = (uint32_t)(bRow * 128);

    for (int kt = 0; kt < KT; kt++) {
        mbar_wait(mb0 + 8 * (kt % S), (uint32_t)((kt / S) & 1));
        // refill the stage freed at the end of the previous iteration
        if (tid == 0) {
            int j = kt + S - 1;
            if (j < KT) {
                uint32_t mb = mb0 + 8 * (j % S);
                uint32_t st = data0 + (j % S) * STAGEB;
                mbar_expect(mb, 32768);
                bulk_g2s(st,         Abase + (size_t)j * TILE_F, 16384, mb);
                bulk_g2s(st + 16384, Bbase + (size_t)j * TILE_F, 16384, mb);
            }
        }
        const uint32_t stb = data0 + (kt % S) * STAGEB;
        const uint32_t aT = stb + aB0;
        const uint32_t bT = stb + 16384 + bB0;
#pragma unroll
        for (int ks = 0; ks < 4; ks++) {
            const uint32_t ak = ((uint32_t)(ks * 32) + aOff) ^ aXor;
            const uint32_t bk = ((uint32_t)(ks * 32) + bOff) ^ bXor;
            uint32_t ah[2][4], bh[2][4];
            ldsm4(ah[0][0], ah[0][1], ah[0][2], ah[0][3], aT + ak);
            ldsm4(ah[1][0], ah[1][1], ah[1][2], ah[1][3], aT + 16 * 128 + ak);
            ldsm4(bh[0][0], bh[0][1], bh[0][2], bh[0][3], bT + bk);
            ldsm4(bh[1][0], bh[1][1], bh[1][2], bh[1][3], bT + 16 * 128 + bk);
#pragma unroll
            for (int mi = 0; mi < 2; mi++)
#pragma unroll
                for (int ni = 0; ni < 4; ni++) {
                    const int p = ni >> 1, q = (ni & 1) * 2;
                    mma_tf32(acc[mi][ni][0], acc[mi][ni][1], acc[mi][ni][2], acc[mi][ni][3],
                             ah[mi][0], ah[mi][1], ah[mi][2], ah[mi][3],
                             bh[p][q], bh[p][q + 1]);
                }
        }
        __syncthreads();
    }

    // Epilogue
#pragma unroll
    for (int mi = 0; mi < 2; mi++) {
#pragma unroll
        for (int ni = 0; ni < 4; ni++) {
#pragma unroll
            for (int half = 0; half < 2; half++) {
                float v0 = acc[mi][ni][half * 2], v1 = acc[mi][ni][half * 2 + 1];
                int mrow = wm + mi * 16 + grp + half * 8;          // 0..127
                int kcol = wn + ni * 8 + tig * 2;                  // 0..127
                if (EPI == 0) {
                    size_t off = (size_t)(blockIdx.y * 128 + mrow) * ldcP
                               + blockIdx.x * 128 + kcol;
                    *(float2*)(C + off) = make_float2(v0, v1);
                } else {
                    int ktile = blockIdx.x * 4 + (kcol >> 5) + blockIdx.z * azC;
                    size_t tb = ((size_t)blockIdx.y * ldcP + ktile) * TILE_F;
                    uint32_t o = sw128((uint32_t)(mrow * 128 + (kcol & 31) * 4));
                    *(float2*)(C + tb + o / 4) = make_float2(tf32r(v0), tf32r(v1));
                }
            }
        }
    }
}

// ---------------------------------------------------------------------------
// Pack megakernel: round h into tiled layout; transpose+round weights tiled.
// ---------------------------------------------------------------------------
constexpr int PB_H   = 4096;
constexpr int PB_WQC = 1024;    // (512/32)*(2048/32)
constexpr int PB_WQU = 1024;    // (2048/32)*(512/32)
constexpr int PB_WK  = 256;
constexpr int PB_WV  = 256;
constexpr int PB_W1  = 4096;
constexpr int PB_W2  = 16384;   // (2048/32)*(8192/32)
constexpr int PB_TOTAL = PB_H + PB_WQC + PB_WQU + PB_WK + PB_WV + PB_W1 + PB_W2;

// src[K][N] -> tiled dst (rows = N dim + nBase, k = K dim), KTt = K/32 tiles.
__device__ __forceinline__ void pk_transpose(const float* __restrict__ src,
                                             float* __restrict__ dst,
                                             int K, int N, int tile, int KTt, int nBase) {
    __shared__ float t[32][33];
    int tx = threadIdx.x & 31, ty = threadIdx.x >> 5;
    int ntx = N / 32;
    int n0 = (tile % ntx) * 32, k0 = (tile / ntx) * 32;
#pragma unroll
    for (int i = ty; i < 32; i += 8)
        t[i][tx] = src[(size_t)(k0 + i) * N + n0 + tx];
    __syncthreads();
#pragma unroll
    for (int i = ty; i < 32; i += 8) {
        int n = nBase + n0 + i;
        int k = k0 + tx;
        size_t tb = ((size_t)(n >> 7) * KTt + (k >> 5)) * TILE_F;
        uint32_t o = sw128((uint32_t)((n & 127) * 128 + (k & 31) * 4));
        dst[tb + o / 4] = tf32r(t[tx][i]);
    }
}

__global__ void __launch_bounds__(256)
pack_kernel(const float* __restrict__ h_in, float* __restrict__ h_t,
            const float* __restrict__ wqc, float* __restrict__ wqc_t,
            const float* __restrict__ wqu, float* __restrict__ wqu_t,
            const float* __restrict__ wk,  const float* __restrict__ wv,
            float* __restrict__ wkv_t,
            const float* __restrict__ w1,  float* __restrict__ w1_t,
            const float* __restrict__ w2,  float* __restrict__ w2_t) {
    int b = blockIdx.x;
    if (b < PB_H) {
        // one row of h (2048 floats), tiled+swizzled into h_t
        int m = b;
        size_t mtb = (size_t)(m >> 7) * 64;
        uint32_t rowo = (uint32_t)((m & 127) * 128);
        const float* srow = h_in + (size_t)m * 2048;
#pragma unroll
        for (int i = 0; i < 8; i++) {
            int k = threadIdx.x * 8 + i;
            size_t tb = (mtb + (k >> 5)) * TILE_F;
            uint32_t o = sw128(rowo + (uint32_t)((k & 31) * 4));
            h_t[tb + o / 4] = tf32r(srow[k]);
        }
        return;
    }
    b -= PB_H;
    if (b < PB_WQC) { pk_transpose(wqc, wqc_t, C_HID, C_QC, b, 64, 0); return; }
    b -= PB_WQC;
    if (b < PB_WQU) { pk_transpose(wqu, wqu_t, C_QC, C_H * C_D, b, 16, 0); return; }
    b -= PB_WQU;
    if (b < PB_WK)  { pk_transpose(wk, wkv_t, C_HID, C_D, b, 64, 0); return; }
    b -= PB_WK;
    if (b < PB_WV)  { pk_transpose(wv, wkv_t, C_HID, C_D, b, 64, 128); return; }
    b -= PB_WV;
    if (b < PB_W1) {
        int g = b / 1024, tile = b % 1024;
        pk_transpose(w1 + (size_t)g * 512 * 2048,
                     w1_t + (size_t)g * 256 * TILE_F,
                     512, 2048, tile, 16, 0);
        return;
    }
    b -= PB_W1;
    pk_transpose(w2, w2_t, C_G * C_INTER, C_HID, b, 256, 0);
}

// ---------------------------------------------------------------------------
// Combined RoPE + RMSNorm for q and k (normal layouts). One warp per row.
// ---------------------------------------------------------------------------
__global__ void __launch_bounds__(256)
rope_kernel(float* __restrict__ q, float* __restrict__ kv,
            const float* __restrict__ qw, const float* __restrict__ kw) {
    int gid  = blockIdx.x * blockDim.x + threadIdx.x;
    int wid  = gid >> 5;
    int lane = threadIdx.x & 31;

    float* row;
    const float* w;
    int pos;
    if (wid < C_TOK * C_H) {
        row = q + (size_t)wid * C_D;
        w = qw;
        pos = (wid / C_H) % C_T;
    } else {
        int wk2 = wid - C_TOK * C_H;
        if (wk2 >= C_TOK) return;
        row = kv + (size_t)wk2 * (2 * C_D);
        w = kw;
        pos = wk2 % C_T;
    }

    float a  = row[lane];
    float b2 = row[lane + 32];
    float c  = row[lane + 64];
    float e  = row[lane + 96];

    double invd = exp(-log(10000.0) * (double)(2 * lane) / 64.0);
    double ang  = (double)pos * invd;
    float cs = (float)cos(ang);
    float sn = (float)sin(ang);

    float r1 = a * cs - b2 * sn;
    float r2 = a * sn + b2 * cs;

    float ss = r1 * r1 + r2 * r2 + c * c + e * e;
#pragma unroll
    for (int off = 16; off; off >>= 1) ss += __shfl_xor_sync(0xffffffffu, ss, off);
    float rms = rsqrtf(ss * (1.0f / 128.0f) + 1e-6f);

    row[lane]      = r1 * rms * w[lane];
    row[lane + 32] = r2 * rms * w[lane + 32];
    row[lane + 64] = c  * rms * w[lane + 64];
    row[lane + 96] = e  * rms * w[lane + 96];
}

// ---------------------------------------------------------------------------
// Attention: block per (t, b); 16 warps = 16 heads; K/V smem chunks of 32.
// Output written tiled+swizzled+tf32-rounded for the w1 GEMM.
// ---------------------------------------------------------------------------
__global__ void __launch_bounds__(512)
attn_kernel(const float* __restrict__ q, const float* __restrict__ kv,
            const float* __restrict__ sink, float* __restrict__ att_t) {
    __shared__ float skv[32 * 2 * C_D];

    int t = blockIdx.x, b = blockIdx.y;
    int h    = threadIdx.x >> 5;
    int lane = threadIdx.x & 31;
    int tid  = threadIdx.x;
    int token = b * C_T + t;

    const float4* q4p = (const float4*)(q + (size_t)token * (C_H * C_D) + h * C_D);
    float4 qv = q4p[lane];

    const float scale = 0.08838834764831845f;
    float m = -1e30f, ssum = 0.f;
    float4 av = make_float4(0.f, 0.f, 0.f, 0.f);

    int s0 = t - (C_WIN - 1);
    if (s0 < 0) s0 = 0;

    for (int c0 = s0; c0 <= t; c0 += 32) {
        int cnt = t - c0 + 1;
        if (cnt > 32) cnt = 32;
        __syncthreads();
        const float4* src = (const float4*)(kv + (size_t)(b * C_T + c0) * (2 * C_D));
        for (int i = tid; i < cnt * 64; i += 512)
            ((float4*)skv)[i] = src[i];
        __syncthreads();

        for (int j = 0; j < cnt; j++) {
            const float4* krow = (const float4*)(skv + j * (2 * C_D));
            float4 kvec = krow[lane];
            float d = qv.x * kvec.x + qv.y * kvec.y + qv.z * kvec.z + qv.w * kvec.w;
#pragma unroll
            for (int off = 16; off; off >>= 1) d += __shfl_xor_sync(0xffffffffu, d, off);
            d *= scale;

            float mn   = fmaxf(m, d);
            float corr = __expf(m - mn);
            float p    = __expf(d - mn);

            float4 vvec = krow[32 + lane];
            ssum = ssum * corr + p;
            av.x = av.x * corr + p * vvec.x;
            av.y = av.y * corr + p * vvec.y;
            av.z = av.z * corr + p * vvec.z;
            av.w = av.w * corr + p * vvec.w;
            m = mn;
        }
    }

    float sl   = sink[h];
    float mn   = fmaxf(m, sl);
    float corr = __expf(m - mn);
    ssum = ssum * corr + __expf(sl - mn);
    float inv = corr / ssum;

    // tiled write: row = token, cols h*128 + 4*lane .. +3
    int ktile = 4 * h + (lane >> 3);
    size_t tb = ((size_t)(token >> 7) * 64 + ktile) * TILE_F;
    uint32_t o = sw128((uint32_t)((token & 127) * 128 + (lane & 7) * 16));
    *(float4*)(att_t + tb + o / 4) =
        make_float4(tf32r(av.x * inv), tf32r(av.y * inv),
                    tf32r(av.z * inv), tf32r(av.w * inv));
}

// ---------------------------------------------------------------------------
extern "C" void kernel_launch(void* const* d_in, const int* in_sizes, int n_in,
                              void* d_out, int out_size) {
    const float* h_in     = (const float*)d_in[0];
    const float* wq_comp  = (const float*)d_in[1];
    const float* wq_up    = (const float*)d_in[2];
    const float* wk       = (const float*)d_in[3];
    const float* wv       = (const float*)d_in[4];
    const float* q_norm_w = (const float*)d_in[5];
    const float* k_norm_w = (const float*)d_in[6];
    const float* sink     = (const float*)d_in[7];
    const float* out_w1   = (const float*)d_in[8];
    const float* out_w2   = (const float*)d_in[9];
    float* out = (float*)d_out;

    float *h_t, *hc_t, *att_t, *y1_t, *wqc_t, *wqu_t, *wkv_t, *w1_t, *w2_t, *q, *kv;
    cudaGetSymbolAddress((void**)&h_t,   g_h_t);
    cudaGetSymbolAddress((void**)&hc_t,  g_hc_t);
    cudaGetSymbolAddress((void**)&att_t, g_att_t);
    cudaGetSymbolAddress((void**)&y1_t,  g_y1_t);
    cudaGetSymbolAddress((void**)&wqc_t, g_wqc_t);
    cudaGetSymbolAddress((void**)&wqu_t, g_wqu_t);
    cudaGetSymbolAddress((void**)&wkv_t, g_wkv_t);
    cudaGetSymbolAddress((void**)&w1_t,  g_w1_t);
    cudaGetSymbolAddress((void**)&w2_t,  g_w2_t);
    cudaGetSymbolAddress((void**)&q,     g_q);
    cudaGetSymbolAddress((void**)&kv,    g_kv);

    constexpr int SM_TMA = 1024 + 4 * 32768;   // 132096 B
    cudaFuncSetAttribute(gemm_tma<0>, cudaFuncAttributeMaxDynamicSharedMemorySize, SM_TMA);
    cudaFuncSetAttribute(gemm_tma<1>, cudaFuncAttributeMaxDynamicSharedMemorySize, SM_TMA);

    // [0] pack: round h + all weights into tiled/swizzled layout
    pack_kernel<<<PB_TOTAL, 256>>>(h_in, h_t, wq_comp, wqc_t, wq_up, wqu_t,
                                   wk, wv, wkv_t, out_w1, w1_t, out_w2, w2_t);

    // [1] hc = h @ wq_comp  -> tiled rounded   (KT=64)
    gemm_tma<1><<<dim3(4, 32), 512, SM_TMA>>>(
        h_t, wqc_t, hc_t, 64, 64, 64, 0, 0, /*ldcT*/16, 0);

    // [2] q = hc @ wq_up    -> normal          (KT=16)
    gemm_tma<0><<<dim3(16, 32), 512, SM_TMA>>>(
        hc_t, wqu_t, q, 16, 16, 16, 0, 0, /*ldc*/C_H * C_D, 0);

    // [3] kv = h @ wkv      -> normal          (KT=64)
    gemm_tma<0><<<dim3(2, 32), 512, SM_TMA>>>(
        h_t, wkv_t, kv, 64, 64, 64, 0, 0, /*ldc*/2 * C_D, 0);

    // [4] RoPE + RMSNorm (q + k combined)
    {
        int warps = C_TOK * C_H + C_TOK;
        rope_kernel<<<(warps * 32 + 255) / 256, 256>>>(q, kv, q_norm_w, k_norm_w);
    }

    // [5] attention -> att tiled rounded
    attn_kernel<<<dim3(C_T, C_B), 512>>>(q, kv, sink, att_t);

    // [6] y1 = grouped att @ w1 -> tiled rounded (z = group, KT=16)
    gemm_tma<1><<<dim3(16, 32, C_G), 512, SM_TMA>>>(
        att_t, w1_t, y1_t, 16, 64, 16, /*azA*/16, /*azB*/256, /*ldcT*/256, /*azC*/64);

    // [7] out = y1 @ out_w2 -> normal           (KT=256)
    gemm_tma<0><<<dim3(16, 32), 512, SM_TMA>>>(
        y1_t, w2_t, out, 256, 256, 256, 0, 0, /*ldc*/C_HID, 0);
}

// round 11
// speedup vs baseline: 1.6765x; 1.2099x over previous
#include <cuda_runtime.h>
#include <cuda_fp16.h>
#include <math.h>
#include <stdint.h>

// Problem constants
constexpr int C_B    = 2;
constexpr int C_T    = 2048;
constexpr int C_HID  = 2048;
constexpr int C_H    = 16;
constexpr int C_D    = 128;
constexpr int C_WIN  = 512;
constexpr int C_QC   = 512;
constexpr int C_G    = 4;
constexpr int C_INTER= 2048;
constexpr int C_TOK  = C_B * C_T;
constexpr int TILE_H = 8192;            // halves per 16KB [128 rows x 64 k] tile

// ---------------------------------------------------------------------------
// Scratch. Tiled half matrices: tile (rt, kt) of [R][K] at
// ((rt*KT + kt)*8192 + sw128((r%128)*128 + (k%64)*2)/2). 128B rows, SW128.
// ---------------------------------------------------------------------------
__device__ __align__(1024) __half g_h_t  [(size_t)32 * 32 * TILE_H];   // h   [4096][2048]
__device__ __align__(1024) __half g_hc_t [(size_t)32 * 8  * TILE_H];   // hc  [4096][512]
__device__ __align__(1024) __half g_att_t[(size_t)32 * 32 * TILE_H];   // att [4096][2048]
__device__ __align__(1024) __half g_y1_t [(size_t)32 * 128* TILE_H];   // y1  [4096][8192]
__device__ __align__(1024) __half g_wqc_t[(size_t)4  * 32 * TILE_H];   // wqcT[512][2048]
__device__ __align__(1024) __half g_wqu_t[(size_t)16 * 8  * TILE_H];   // wquT[2048][512]
__device__ __align__(1024) __half g_wkv_t[(size_t)2  * 32 * TILE_H];   // wkvT[256][2048]
__device__ __align__(1024) __half g_w1_t [(size_t)4 * 16 * 8 * TILE_H];// w1T/g [2048][512]
__device__ __align__(1024) __half g_w2_t [(size_t)16 * 128* TILE_H];   // w2T [2048][8192]
__device__ float g_q [C_TOK * C_H * C_D];
__device__ float g_kv[C_TOK * 2 * C_D];

// ---------------------------------------------------------------------------
__device__ __forceinline__ uint32_t sw128(uint32_t off) {
    return off ^ ((off >> 3) & 0x70);
}

__device__ __forceinline__ void mma_f16(float& c0, float& c1, float& c2, float& c3,
                                        uint32_t a0, uint32_t a1, uint32_t a2, uint32_t a3,
                                        uint32_t b0, uint32_t b1) {
    asm volatile(
        "mma.sync.aligned.m16n8k16.row.col.f32.f16.f16.f32 "
        "{%0,%1,%2,%3}, {%4,%5,%6,%7}, {%8,%9}, {%0,%1,%2,%3};"
        : "+f"(c0), "+f"(c1), "+f"(c2), "+f"(c3)
        : "r"(a0), "r"(a1), "r"(a2), "r"(a3), "r"(b0), "r"(b1));
}

__device__ __forceinline__ void ldsm4(uint32_t& r0, uint32_t& r1, uint32_t& r2, uint32_t& r3,
                                      uint32_t addr) {
    asm volatile("ldmatrix.sync.aligned.m8n8.x4.shared.b16 {%0,%1,%2,%3}, [%4];"
                 : "=r"(r0), "=r"(r1), "=r"(r2), "=r"(r3) : "r"(addr));
}

__device__ __forceinline__ void mbar_init(uint32_t a, uint32_t cnt) {
    asm volatile("mbarrier.init.shared.b64 [%0], %1;" :: "r"(a), "r"(cnt) : "memory");
}
__device__ __forceinline__ void mbar_expect(uint32_t a, uint32_t bytes) {
    asm volatile("mbarrier.arrive.expect_tx.shared.b64 _, [%0], %1;"
                 :: "r"(a), "r"(bytes) : "memory");
}
__device__ __forceinline__ void mbar_wait(uint32_t a, uint32_t parity) {
    uint32_t done;
    asm volatile(
        "{\n\t.reg .pred p;\n\t"
        "mbarrier.try_wait.parity.acquire.cta.shared::cta.b64 p, [%1], %2;\n\t"
        "selp.b32 %0, 1, 0, p;\n\t}"
        : "=r"(done) : "r"(a), "r"(parity) : "memory");
    if (!done) {
        asm volatile(
            "{\n\t.reg .pred P1;\n\t"
            "WAIT_LOOP_%=:\n\t"
            "mbarrier.try_wait.parity.acquire.cta.shared::cta.b64 P1, [%0], %1, 0x989680;\n\t"
            "@P1 bra.uni WAIT_DONE_%=;\n\t"
            "bra.uni WAIT_LOOP_%=;\n\t"
            "WAIT_DONE_%=:\n\t}"
            :: "r"(a), "r"(parity) : "memory");
    }
}
__device__ __forceinline__ void bulk_g2s(uint32_t dst, const void* src, uint32_t bytes,
                                         uint32_t mbar) {
    asm volatile(
        "cp.async.bulk.shared::cta.global.mbarrier::complete_tx::bytes [%0], [%1], %2, [%3];"
        :: "r"(dst), "l"(src), "r"(bytes), "r"(mbar) : "memory");
}

// ---------------------------------------------------------------------------
// TMA-fed fp16 GEMM on tiled operands. 128x128 CTA tile, K-chunk = 64 halves,
// 512 threads (4x4 warps, warp tile 32x32). EPI 0: fp32 C. EPI 1: half tiled C.
// ---------------------------------------------------------------------------
template<int EPI>
__global__ void __launch_bounds__(512)
gemm_tma(const __half* __restrict__ A, const __half* __restrict__ B,
         float* __restrict__ Cf, __half* __restrict__ Ch,
         int KT, int ldaT, int ldbT, int azA, int azB, int ldcP, int azC) {
    constexpr int S = 4;
    constexpr int STAGEB = 2 * 16384;

    extern __shared__ __align__(16) char smc[];
    const uint32_t sbase = (uint32_t)__cvta_generic_to_shared(smc);
    const uint32_t mb0   = sbase;
    const uint32_t data0 = sbase + 1024;

    const int tid  = threadIdx.x;
    const int warp = tid >> 5;
    const int lane = tid & 31;
    const int wm   = (warp >> 2) * 32;
    const int wn   = (warp & 3) * 32;
    const int grp  = lane >> 2;
    const int tig  = lane & 3;

    const __half* Abase = A + ((size_t)blockIdx.y * ldaT + (size_t)blockIdx.z * azA) * TILE_H;
    const __half* Bbase = B + ((size_t)blockIdx.x * ldbT + (size_t)blockIdx.z * azB) * TILE_H;

    if (tid == 0) {
        for (int s = 0; s < S; s++) mbar_init(mb0 + 8 * s, 1);
    }
    __syncthreads();
    if (tid == 0) {
        for (int i = 0; i < S - 1 && i < KT; i++) {
            uint32_t mb = mb0 + 8 * i;
            mbar_expect(mb, 32768);
            bulk_g2s(data0 + i * STAGEB,         Abase + (size_t)i * TILE_H, 16384, mb);
            bulk_g2s(data0 + i * STAGEB + 16384, Bbase + (size_t)i * TILE_H, 16384, mb);
        }
    }

    float acc[2][4][4];
#pragma unroll
    for (int i = 0; i < 2; i++)
#pragma unroll
        for (int j = 0; j < 4; j++)
#pragma unroll
            for (int r = 0; r < 4; r++) acc[i][j][r] = 0.f;

    // ldmatrix addressing in swizzled [128 x 128B] tile
    const int aRow = wm + (lane & 15);
    const uint32_t aOff = (uint32_t)((lane >> 4) * 16);
    const uint32_t aXor = (uint32_t)((aRow & 7) << 4);
    const uint32_t aB0  = (uint32_t)(aRow * 128);
    const int bRow = wn + ((lane >> 4) & 1) * 8 + (lane & 7);
    const uint32_t bOff = (uint32_t)(((lane >> 3) & 1) * 16);
    const uint32_t bXor = (uint32_t)((lane & 7) << 4);
    const uint32_t bB0  = (uint32_t)(bRow * 128);

    for (int kt = 0; kt < KT; kt++) {
        mbar_wait(mb0 + 8 * (kt % S), (uint32_t)((kt / S) & 1));
        if (tid == 0) {
            int j = kt + S - 1;
            if (j < KT) {
                uint32_t mb = mb0 + 8 * (j % S);
                uint32_t st = data0 + (j % S) * STAGEB;
                mbar_expect(mb, 32768);
                bulk_g2s(st,         Abase + (size_t)j * TILE_H, 16384, mb);
                bulk_g2s(st + 16384, Bbase + (size_t)j * TILE_H, 16384, mb);
            }
        }
        const uint32_t stb = data0 + (kt % S) * STAGEB;
        const uint32_t aT = stb + aB0;
        const uint32_t bT = stb + 16384 + bB0;
#pragma unroll
        for (int ks = 0; ks < 4; ks++) {            // 4 x k16 = 64 halves
            const uint32_t ak = ((uint32_t)(ks * 32) + aOff) ^ aXor;
            const uint32_t bk = ((uint32_t)(ks * 32) + bOff) ^ bXor;
            uint32_t ah[2][4], bh[2][4];
            ldsm4(ah[0][0], ah[0][1], ah[0][2], ah[0][3], aT + ak);
            ldsm4(ah[1][0], ah[1][1], ah[1][2], ah[1][3], aT + 16 * 128 + ak);
            ldsm4(bh[0][0], bh[0][1], bh[0][2], bh[0][3], bT + bk);
            ldsm4(bh[1][0], bh[1][1], bh[1][2], bh[1][3], bT + 16 * 128 + bk);
#pragma unroll
            for (int mi = 0; mi < 2; mi++)
#pragma unroll
                for (int ni = 0; ni < 4; ni++) {
                    const int p = ni >> 1, q = (ni & 1) * 2;
                    mma_f16(acc[mi][ni][0], acc[mi][ni][1], acc[mi][ni][2], acc[mi][ni][3],
                            ah[mi][0], ah[mi][1], ah[mi][2], ah[mi][3],
                            bh[p][q], bh[p][q + 1]);
                }
        }
        __syncthreads();
    }

    // Epilogue
#pragma unroll
    for (int mi = 0; mi < 2; mi++) {
#pragma unroll
        for (int ni = 0; ni < 4; ni++) {
#pragma unroll
            for (int half_ = 0; half_ < 2; half_++) {
                float v0 = acc[mi][ni][half_ * 2], v1 = acc[mi][ni][half_ * 2 + 1];
                int mrow = wm + mi * 16 + grp + half_ * 8;
                int kcol = wn + ni * 8 + tig * 2;
                if (EPI == 0) {
                    size_t off = (size_t)(blockIdx.y * 128 + mrow) * ldcP
                               + blockIdx.x * 128 + kcol;
                    *(float2*)(Cf + off) = make_float2(v0, v1);
                } else {
                    int ktile = blockIdx.x * 2 + (kcol >> 6) + blockIdx.z * azC;
                    size_t tb = ((size_t)blockIdx.y * ldcP + ktile) * TILE_H;
                    uint32_t o = sw128((uint32_t)(mrow * 128 + (kcol & 63) * 2));
                    __half2 hv;
                    hv.x = __float2half_rn(v0);
                    hv.y = __float2half_rn(v1);
                    *(__half2*)((char*)Ch + tb * 2 + o) = hv;
                }
            }
        }
    }
}

// ---------------------------------------------------------------------------
// Pack megakernel
// ---------------------------------------------------------------------------
constexpr int PB_H   = 4096;
constexpr int PB_WQC = 1024;
constexpr int PB_WQU = 1024;
constexpr int PB_WK  = 256;
constexpr int PB_WV  = 256;
constexpr int PB_W1  = 4096;
constexpr int PB_W2  = 16384;
constexpr int PB_TOTAL = PB_H + PB_WQC + PB_WQU + PB_WK + PB_WV + PB_W1 + PB_W2;

// src[K][N] -> tiled half dst (row dim = N + nBase, k dim = K), KTt = K/64.
__device__ __forceinline__ void pk_transpose(const float* __restrict__ src,
                                             __half* __restrict__ dst,
                                             int K, int N, int tile, int KTt, int nBase) {
    __shared__ float t[32][33];
    int tx = threadIdx.x & 31, ty = threadIdx.x >> 5;
    int ntx = N / 32;
    int n0 = (tile % ntx) * 32, k0 = (tile / ntx) * 32;
#pragma unroll
    for (int i = ty; i < 32; i += 8)
        t[i][tx] = src[(size_t)(k0 + i) * N + n0 + tx];
    __syncthreads();
#pragma unroll
    for (int i = ty; i < 32; i += 8) {
        int n = nBase + n0 + i;
        int k = k0 + tx;
        size_t tb = ((size_t)(n >> 7) * KTt + (k >> 6)) * TILE_H;
        uint32_t o = sw128((uint32_t)((n & 127) * 128 + (k & 63) * 2));
        *(__half*)((char*)dst + tb * 2 + o) = __float2half_rn(t[tx][i]);
    }
}

__global__ void __launch_bounds__(256)
pack_kernel(const float* __restrict__ h_in, __half* __restrict__ h_t,
            const float* __restrict__ wqc, __half* __restrict__ wqc_t,
            const float* __restrict__ wqu, __half* __restrict__ wqu_t,
            const float* __restrict__ wk,  const float* __restrict__ wv,
            __half* __restrict__ wkv_t,
            const float* __restrict__ w1,  __half* __restrict__ w1_t,
            const float* __restrict__ w2,  __half* __restrict__ w2_t) {
    int b = blockIdx.x;
    if (b < PB_H) {
        int m = b;
        size_t mtb = (size_t)(m >> 7) * 32;
        uint32_t rowo = (uint32_t)((m & 127) * 128);
        const float* srow = h_in + (size_t)m * 2048;
#pragma unroll
        for (int i = 0; i < 8; i++) {
            int k = threadIdx.x * 8 + i;
            size_t tb = (mtb + (k >> 6)) * TILE_H;
            uint32_t o = sw128(rowo + (uint32_t)((k & 63) * 2));
            *(__half*)((char*)h_t + tb * 2 + o) = __float2half_rn(srow[k]);
        }
        return;
    }
    b -= PB_H;
    if (b < PB_WQC) { pk_transpose(wqc, wqc_t, C_HID, C_QC, b, 32, 0); return; }
    b -= PB_WQC;
    if (b < PB_WQU) { pk_transpose(wqu, wqu_t, C_QC, C_H * C_D, b, 8, 0); return; }
    b -= PB_WQU;
    if (b < PB_WK)  { pk_transpose(wk, wkv_t, C_HID, C_D, b, 32, 0); return; }
    b -= PB_WK;
    if (b < PB_WV)  { pk_transpose(wv, wkv_t, C_HID, C_D, b, 32, 128); return; }
    b -= PB_WV;
    if (b < PB_W1) {
        int g = b / 1024, tile = b % 1024;
        pk_transpose(w1 + (size_t)g * 512 * 2048,
                     w1_t + (size_t)g * 128 * TILE_H,
                     512, 2048, tile, 8, 0);
        return;
    }
    b -= PB_W1;
    pk_transpose(w2, w2_t, C_G * C_INTER, C_HID, b, 128, 0);
}

// ---------------------------------------------------------------------------
// Combined RoPE + RMSNorm for q and k. One warp per row.
// ---------------------------------------------------------------------------
__global__ void __launch_bounds__(256)
rope_kernel(float* __restrict__ q, float* __restrict__ kv,
            const float* __restrict__ qw, const float* __restrict__ kw) {
    int gid  = blockIdx.x * blockDim.x + threadIdx.x;
    int wid  = gid >> 5;
    int lane = threadIdx.x & 31;

    float* row;
    const float* w;
    int pos;
    if (wid < C_TOK * C_H) {
        row = q + (size_t)wid * C_D;
        w = qw;
        pos = (wid / C_H) % C_T;
    } else {
        int wk2 = wid - C_TOK * C_H;
        if (wk2 >= C_TOK) return;
        row = kv + (size_t)wk2 * (2 * C_D);
        w = kw;
        pos = wk2 % C_T;
    }

    float a  = row[lane];
    float b2 = row[lane + 32];
    float c  = row[lane + 64];
    float e  = row[lane + 96];

    double invd = exp(-log(10000.0) * (double)(2 * lane) / 64.0);
    double ang  = (double)pos * invd;
    float cs = (float)cos(ang);
    float sn = (float)sin(ang);

    float r1 = a * cs - b2 * sn;
    float r2 = a * sn + b2 * cs;

    float ss = r1 * r1 + r2 * r2 + c * c + e * e;
#pragma unroll
    for (int off = 16; off; off >>= 1) ss += __shfl_xor_sync(0xffffffffu, ss, off);
    float rms = rsqrtf(ss * (1.0f / 128.0f) + 1e-6f);

    row[lane]      = r1 * rms * w[lane];
    row[lane + 32] = r2 * rms * w[lane + 32];
    row[lane + 64] = c  * rms * w[lane + 64];
    row[lane + 96] = e  * rms * w[lane + 96];
}

// ---------------------------------------------------------------------------
// Attention: block per (t, b); 16 warps = 16 heads; smem K/V chunks of 32.
// Output written tiled+swizzled as half for the w1 GEMM.
// ---------------------------------------------------------------------------
__global__ void __launch_bounds__(512)
attn_kernel(const float* __restrict__ q, const float* __restrict__ kv,
            const float* __restrict__ sink, __half* __restrict__ att_t) {
    __shared__ float skv[32 * 2 * C_D];

    int t = blockIdx.x, b = blockIdx.y;
    int h    = threadIdx.x >> 5;
    int lane = threadIdx.x & 31;
    int tid  = threadIdx.x;
    int token = b * C_T + t;

    const float4* q4p = (const float4*)(q + (size_t)token * (C_H * C_D) + h * C_D);
    float4 qv = q4p[lane];

    const float scale = 0.08838834764831845f;
    float m = -1e30f, ssum = 0.f;
    float4 av = make_float4(0.f, 0.f, 0.f, 0.f);

    int s0 = t - (C_WIN - 1);
    if (s0 < 0) s0 = 0;

    for (int c0 = s0; c0 <= t; c0 += 32) {
        int cnt = t - c0 + 1;
        if (cnt > 32) cnt = 32;
        __syncthreads();
        const float4* src = (const float4*)(kv + (size_t)(b * C_T + c0) * (2 * C_D));
        for (int i = tid; i < cnt * 64; i += 512)
            ((float4*)skv)[i] = src[i];
        __syncthreads();

        for (int j = 0; j < cnt; j++) {
            const float4* krow = (const float4*)(skv + j * (2 * C_D));
            float4 kvec = krow[lane];
            float d = qv.x * kvec.x + qv.y * kvec.y + qv.z * kvec.z + qv.w * kvec.w;
#pragma unroll
            for (int off = 16; off; off >>= 1) d += __shfl_xor_sync(0xffffffffu, d, off);
            d *= scale;

            float mn   = fmaxf(m, d);
            float corr = __expf(m - mn);
            float p    = __expf(d - mn);

            float4 vvec = krow[32 + lane];
            ssum = ssum * corr + p;
            av.x = av.x * corr + p * vvec.x;
            av.y = av.y * corr + p * vvec.y;
            av.z = av.z * corr + p * vvec.z;
            av.w = av.w * corr + p * vvec.w;
            m = mn;
        }
    }

    float sl   = sink[h];
    float mn   = fmaxf(m, sl);
    float corr = __expf(m - mn);
    ssum = ssum * corr + __expf(sl - mn);
    float inv = corr / ssum;

    // tiled half write: row = token, cols h*128 + 4*lane .. +3
    int col = h * 128 + lane * 4;
    int ktile = col >> 6;
    size_t tb = ((size_t)(token >> 7) * 32 + ktile) * TILE_H;
    uint32_t o = sw128((uint32_t)((token & 127) * 128 + (col & 63) * 2));
    __half2 lo, hi;
    lo.x = __float2half_rn(av.x * inv);
    lo.y = __float2half_rn(av.y * inv);
    hi.x = __float2half_rn(av.z * inv);
    hi.y = __float2half_rn(av.w * inv);
    uint2 pk;
    pk.x = *(uint32_t*)&lo;
    pk.y = *(uint32_t*)&hi;
    *(uint2*)((char*)att_t + tb * 2 + o) = pk;
}

// ---------------------------------------------------------------------------
extern "C" void kernel_launch(void* const* d_in, const int* in_sizes, int n_in,
                              void* d_out, int out_size) {
    const float* h_in     = (const float*)d_in[0];
    const float* wq_comp  = (const float*)d_in[1];
    const float* wq_up    = (const float*)d_in[2];
    const float* wk       = (const float*)d_in[3];
    const float* wv       = (const float*)d_in[4];
    const float* q_norm_w = (const float*)d_in[5];
    const float* k_norm_w = (const float*)d_in[6];
    const float* sink     = (const float*)d_in[7];
    const float* out_w1   = (const float*)d_in[8];
    const float* out_w2   = (const float*)d_in[9];
    float* out = (float*)d_out;

    __half *h_t, *hc_t, *att_t, *y1_t, *wqc_t, *wqu_t, *wkv_t, *w1_t, *w2_t;
    float *q, *kv;
    cudaGetSymbolAddress((void**)&h_t,   g_h_t);
    cudaGetSymbolAddress((void**)&hc_t,  g_hc_t);
    cudaGetSymbolAddress((void**)&att_t, g_att_t);
    cudaGetSymbolAddress((void**)&y1_t,  g_y1_t);
    cudaGetSymbolAddress((void**)&wqc_t, g_wqc_t);
    cudaGetSymbolAddress((void**)&wqu_t, g_wqu_t);
    cudaGetSymbolAddress((void**)&wkv_t, g_wkv_t);
    cudaGetSymbolAddress((void**)&w1_t,  g_w1_t);
    cudaGetSymbolAddress((void**)&w2_t,  g_w2_t);
    cudaGetSymbolAddress((void**)&q,     g_q);
    cudaGetSymbolAddress((void**)&kv,    g_kv);

    constexpr int SM_TMA = 1024 + 4 * 32768;   // 132096 B
    cudaFuncSetAttribute(gemm_tma<0>, cudaFuncAttributeMaxDynamicSharedMemorySize, SM_TMA);
    cudaFuncSetAttribute(gemm_tma<1>, cudaFuncAttributeMaxDynamicSharedMemorySize, SM_TMA);

    // [0] pack: round-to-half h + all weights into tiled/swizzled layout
    pack_kernel<<<PB_TOTAL, 256>>>(h_in, h_t, wq_comp, wqc_t, wq_up, wqu_t,
                                   wk, wv, wkv_t, out_w1, w1_t, out_w2, w2_t);

    // [1] hc = h @ wq_comp  -> half tiled (KT=32)
    gemm_tma<1><<<dim3(4, 32), 512, SM_TMA>>>(
        h_t, wqc_t, nullptr, hc_t, 32, 32, 32, 0, 0, /*ldcT*/8, 0);

    // [2] q = hc @ wq_up    -> fp32 (KT=8)
    gemm_tma<0><<<dim3(16, 32), 512, SM_TMA>>>(
        hc_t, wqu_t, q, nullptr, 8, 8, 8, 0, 0, /*ldc*/C_H * C_D, 0);

    // [3] kv = h @ wkv      -> fp32 (KT=32)
    gemm_tma<0><<<dim3(2, 32), 512, SM_TMA>>>(
        h_t, wkv_t, kv, nullptr, 32, 32, 32, 0, 0, /*ldc*/2 * C_D, 0);

    // [4] RoPE + RMSNorm
    {
        int warps = C_TOK * C_H + C_TOK;
        rope_kernel<<<(warps * 32 + 255) / 256, 256>>>(q, kv, q_norm_w, k_norm_w);
    }

    // [5] attention -> att half tiled (profiled launch)
    attn_kernel<<<dim3(C_T, C_B), 512>>>(q, kv, sink, att_t);

    // [6] y1 = grouped att @ w1 -> half tiled (z = group, KT=8)
    gemm_tma<1><<<dim3(16, 32, C_G), 512, SM_TMA>>>(
        att_t, w1_t, nullptr, y1_t, 8, 32, 8, /*azA*/8, /*azB*/128, /*ldcT*/128, /*azC*/32);

    // [7] out = y1 @ out_w2 -> fp32 (KT=128)
    gemm_tma<0><<<dim3(16, 32), 512, SM_TMA>>>(
        y1_t, w2_t, out, nullptr, 128, 128, 128, 0, 0, /*ldc*/C_HID, 0);
}

// round 12
// speedup vs baseline: 4.0888x; 2.4390x over previous
#include <cuda_runtime.h>
#include <cuda_fp16.h>
#include <math.h>
#include <stdint.h>

// Problem constants
constexpr int C_B    = 2;
constexpr int C_T    = 2048;
constexpr int C_HID  = 2048;
constexpr int C_H    = 16;
constexpr int C_D    = 128;
constexpr int C_WIN  = 512;
constexpr int C_QC   = 512;
constexpr int C_G    = 4;
constexpr int C_INTER= 2048;
constexpr int C_TOK  = C_B * C_T;
constexpr int TILE_H = 8192;            // halves per 16KB GEMM tile [128 x 64]

// ---------------------------------------------------------------------------
// Scratch
// ---------------------------------------------------------------------------
__device__ __align__(1024) __half g_h_t  [(size_t)32 * 32 * TILE_H];
__device__ __align__(1024) __half g_hc_t [(size_t)32 * 8  * TILE_H];
__device__ __align__(1024) __half g_att_t[(size_t)32 * 32 * TILE_H];
__device__ __align__(1024) __half g_y1_t [(size_t)32 * 128* TILE_H];
__device__ __align__(1024) __half g_wqc_t[(size_t)4  * 32 * TILE_H];
__device__ __align__(1024) __half g_wqu_t[(size_t)16 * 8  * TILE_H];
__device__ __align__(1024) __half g_wkv_t[(size_t)2  * 32 * TILE_H];
__device__ __align__(1024) __half g_w1_t [(size_t)4 * 16 * 8 * TILE_H];
__device__ __align__(1024) __half g_w2_t [(size_t)16 * 128* TILE_H];
__device__ float g_q [C_TOK * C_H * C_D];
__device__ float g_kv[C_TOK * 2 * C_D];
// Attention tiles: [64 rows x 256B] fp16, chunk-swizzled (chunk ^ (row&7))
__device__ __align__(1024) __half g_qs[(size_t)C_B * C_H * 32 * 8192];  // scaled q
__device__ __align__(1024) __half g_ks[(size_t)C_B * 32 * 8192];
__device__ __align__(1024) __half g_vs[(size_t)C_B * 32 * 8192];

// ---------------------------------------------------------------------------
__device__ __forceinline__ uint32_t sw128(uint32_t off) {
    return off ^ ((off >> 3) & 0x70);
}

__device__ __forceinline__ void mma_f16(float& c0, float& c1, float& c2, float& c3,
                                        uint32_t a0, uint32_t a1, uint32_t a2, uint32_t a3,
                                        uint32_t b0, uint32_t b1) {
    asm volatile(
        "mma.sync.aligned.m16n8k16.row.col.f32.f16.f16.f32 "
        "{%0,%1,%2,%3}, {%4,%5,%6,%7}, {%8,%9}, {%0,%1,%2,%3};"
        : "+f"(c0), "+f"(c1), "+f"(c2), "+f"(c3)
        : "r"(a0), "r"(a1), "r"(a2), "r"(a3), "r"(b0), "r"(b1));
}

__device__ __forceinline__ void ldsm4(uint32_t& r0, uint32_t& r1, uint32_t& r2, uint32_t& r3,
                                      uint32_t addr) {
    asm volatile("ldmatrix.sync.aligned.m8n8.x4.shared.b16 {%0,%1,%2,%3}, [%4];"
                 : "=r"(r0), "=r"(r1), "=r"(r2), "=r"(r3) : "r"(addr));
}
__device__ __forceinline__ void ldsm4t(uint32_t& r0, uint32_t& r1, uint32_t& r2, uint32_t& r3,
                                       uint32_t addr) {
    asm volatile("ldmatrix.sync.aligned.m8n8.x4.trans.shared.b16 {%0,%1,%2,%3}, [%4];"
                 : "=r"(r0), "=r"(r1), "=r"(r2), "=r"(r3) : "r"(addr));
}

__device__ __forceinline__ void mbar_init(uint32_t a, uint32_t cnt) {
    asm volatile("mbarrier.init.shared.b64 [%0], %1;" :: "r"(a), "r"(cnt) : "memory");
}
__device__ __forceinline__ void mbar_expect(uint32_t a, uint32_t bytes) {
    asm volatile("mbarrier.arrive.expect_tx.shared.b64 _, [%0], %1;"
                 :: "r"(a), "r"(bytes) : "memory");
}
__device__ __forceinline__ void mbar_wait(uint32_t a, uint32_t parity) {
    uint32_t done;
    asm volatile(
        "{\n\t.reg .pred p;\n\t"
        "mbarrier.try_wait.parity.acquire.cta.shared::cta.b64 p, [%1], %2;\n\t"
        "selp.b32 %0, 1, 0, p;\n\t}"
        : "=r"(done) : "r"(a), "r"(parity) : "memory");
    if (!done) {
        asm volatile(
            "{\n\t.reg .pred P1;\n\t"
            "WAIT_LOOP_%=:\n\t"
            "mbarrier.try_wait.parity.acquire.cta.shared::cta.b64 P1, [%0], %1, 0x989680;\n\t"
            "@P1 bra.uni WAIT_DONE_%=;\n\t"
            "bra.uni WAIT_LOOP_%=;\n\t"
            "WAIT_DONE_%=:\n\t}"
            :: "r"(a), "r"(parity) : "memory");
    }
}
__device__ __forceinline__ void bulk_g2s(uint32_t dst, const void* src, uint32_t bytes,
                                         uint32_t mbar) {
    asm volatile(
        "cp.async.bulk.shared::cta.global.mbarrier::complete_tx::bytes [%0], [%1], %2, [%3];"
        :: "r"(dst), "l"(src), "r"(bytes), "r"(mbar) : "memory");
}

// ---------------------------------------------------------------------------
// TMA-fed fp16 GEMM. S=3 stages, 2 CTAs/SM target.
// ---------------------------------------------------------------------------
template<int EPI>
__global__ void __launch_bounds__(512, 2)
gemm_tma(const __half* __restrict__ A, const __half* __restrict__ B,
         float* __restrict__ Cf, __half* __restrict__ Ch,
         int KT, int ldaT, int ldbT, int azA, int azB, int ldcP, int azC) {
    constexpr int S = 3;
    constexpr int STAGEB = 2 * 16384;

    extern __shared__ __align__(16) char smc[];
    const uint32_t sbase = (uint32_t)__cvta_generic_to_shared(smc);
    const uint32_t mb0   = sbase;
    const uint32_t data0 = sbase + 1024;

    const int tid  = threadIdx.x;
    const int warp = tid >> 5;
    const int lane = tid & 31;
    const int wm   = (warp >> 2) * 32;
    const int wn   = (warp & 3) * 32;
    const int grp  = lane >> 2;
    const int tig  = lane & 3;

    const __half* Abase = A + ((size_t)blockIdx.y * ldaT + (size_t)blockIdx.z * azA) * TILE_H;
    const __half* Bbase = B + ((size_t)blockIdx.x * ldbT + (size_t)blockIdx.z * azB) * TILE_H;

    if (tid == 0) {
        for (int s = 0; s < S; s++) mbar_init(mb0 + 8 * s, 1);
    }
    __syncthreads();
    if (tid == 0) {
        for (int i = 0; i < S - 1 && i < KT; i++) {
            uint32_t mb = mb0 + 8 * i;
            mbar_expect(mb, 32768);
            bulk_g2s(data0 + i * STAGEB,         Abase + (size_t)i * TILE_H, 16384, mb);
            bulk_g2s(data0 + i * STAGEB + 16384, Bbase + (size_t)i * TILE_H, 16384, mb);
        }
    }

    float acc[2][4][4];
#pragma unroll
    for (int i = 0; i < 2; i++)
#pragma unroll
        for (int j = 0; j < 4; j++)
#pragma unroll
            for (int r = 0; r < 4; r++) acc[i][j][r] = 0.f;

    const int aRow = wm + (lane & 15);
    const uint32_t aOff = (uint32_t)((lane >> 4) * 16);
    const uint32_t aXor = (uint32_t)((aRow & 7) << 4);
    const uint32_t aB0  = (uint32_t)(aRow * 128);
    const int bRow = wn + ((lane >> 4) & 1) * 8 + (lane & 7);
    const uint32_t bOff = (uint32_t)(((lane >> 3) & 1) * 16);
    const uint32_t bXor = (uint32_t)((lane & 7) << 4);
    const uint32_t bB0  = (uint32_t)(bRow * 128);

    for (int kt = 0; kt < KT; kt++) {
        mbar_wait(mb0 + 8 * (kt % S), (uint32_t)((kt / S) & 1));
        if (tid == 0) {
            int j = kt + S - 1;
            if (j < KT) {
                uint32_t mb = mb0 + 8 * (j % S);
                uint32_t st = data0 + (j % S) * STAGEB;
                mbar_expect(mb, 32768);
                bulk_g2s(st,         Abase + (size_t)j * TILE_H, 16384, mb);
                bulk_g2s(st + 16384, Bbase + (size_t)j * TILE_H, 16384, mb);
            }
        }
        const uint32_t stb = data0 + (kt % S) * STAGEB;
        const uint32_t aT = stb + aB0;
        const uint32_t bT = stb + 16384 + bB0;
#pragma unroll
        for (int ks = 0; ks < 4; ks++) {
            const uint32_t ak = ((uint32_t)(ks * 32) + aOff) ^ aXor;
            const uint32_t bk = ((uint32_t)(ks * 32) + bOff) ^ bXor;
            uint32_t ah[2][4], bh[2][4];
            ldsm4(ah[0][0], ah[0][1], ah[0][2], ah[0][3], aT + ak);
            ldsm4(ah[1][0], ah[1][1], ah[1][2], ah[1][3], aT + 16 * 128 + ak);
            ldsm4(bh[0][0], bh[0][1], bh[0][2], bh[0][3], bT + bk);
            ldsm4(bh[1][0], bh[1][1], bh[1][2], bh[1][3], bT + 16 * 128 + bk);
#pragma unroll
            for (int mi = 0; mi < 2; mi++)
#pragma unroll
                for (int ni = 0; ni < 4; ni++) {
                    const int p = ni >> 1, q = (ni & 1) * 2;
                    mma_f16(acc[mi][ni][0], acc[mi][ni][1], acc[mi][ni][2], acc[mi][ni][3],
                            ah[mi][0], ah[mi][1], ah[mi][2], ah[mi][3],
                            bh[p][q], bh[p][q + 1]);
                }
        }
        __syncthreads();
    }

#pragma unroll
    for (int mi = 0; mi < 2; mi++) {
#pragma unroll
        for (int ni = 0; ni < 4; ni++) {
#pragma unroll
            for (int half_ = 0; half_ < 2; half_++) {
                float v0 = acc[mi][ni][half_ * 2], v1 = acc[mi][ni][half_ * 2 + 1];
                int mrow = wm + mi * 16 + grp + half_ * 8;
                int kcol = wn + ni * 8 + tig * 2;
                if (EPI == 0) {
                    size_t off = (size_t)(blockIdx.y * 128 + mrow) * ldcP
                               + blockIdx.x * 128 + kcol;
                    *(float2*)(Cf + off) = make_float2(v0, v1);
                } else {
                    int ktile = blockIdx.x * 2 + (kcol >> 6) + blockIdx.z * azC;
                    size_t tb = ((size_t)blockIdx.y * ldcP + ktile) * TILE_H;
                    uint32_t o = sw128((uint32_t)(mrow * 128 + (kcol & 63) * 2));
                    __half2 hv;
                    hv.x = __float2half_rn(v0);
                    hv.y = __float2half_rn(v1);
                    *(__half2*)((char*)Ch + tb * 2 + o) = hv;
                }
            }
        }
    }
}

// ---------------------------------------------------------------------------
// Pack megakernel (unchanged from R11)
// ---------------------------------------------------------------------------
constexpr int PB_H   = 4096;
constexpr int PB_WQC = 1024;
constexpr int PB_WQU = 1024;
constexpr int PB_WK  = 256;
constexpr int PB_WV  = 256;
constexpr int PB_W1  = 4096;
constexpr int PB_W2  = 16384;
constexpr int PB_TOTAL = PB_H + PB_WQC + PB_WQU + PB_WK + PB_WV + PB_W1 + PB_W2;

__device__ __forceinline__ void pk_transpose(const float* __restrict__ src,
                                             __half* __restrict__ dst,
                                             int K, int N, int tile, int KTt, int nBase) {
    __shared__ float t[32][33];
    int tx = threadIdx.x & 31, ty = threadIdx.x >> 5;
    int ntx = N / 32;
    int n0 = (tile % ntx) * 32, k0 = (tile / ntx) * 32;
#pragma unroll
    for (int i = ty; i < 32; i += 8)
        t[i][tx] = src[(size_t)(k0 + i) * N + n0 + tx];
    __syncthreads();
#pragma unroll
    for (int i = ty; i < 32; i += 8) {
        int n = nBase + n0 + i;
        int k = k0 + tx;
        size_t tb = ((size_t)(n >> 7) * KTt + (k >> 6)) * TILE_H;
        uint32_t o = sw128((uint32_t)((n & 127) * 128 + (k & 63) * 2));
        *(__half*)((char*)dst + tb * 2 + o) = __float2half_rn(t[tx][i]);
    }
}

__global__ void __launch_bounds__(256)
pack_kernel(const float* __restrict__ h_in, __half* __restrict__ h_t,
            const float* __restrict__ wqc, __half* __restrict__ wqc_t,
            const float* __restrict__ wqu, __half* __restrict__ wqu_t,
            const float* __restrict__ wk,  const float* __restrict__ wv,
            __half* __restrict__ wkv_t,
            const float* __restrict__ w1,  __half* __restrict__ w1_t,
            const float* __restrict__ w2,  __half* __restrict__ w2_t) {
    int b = blockIdx.x;
    if (b < PB_H) {
        int m = b;
        size_t mtb = (size_t)(m >> 7) * 32;
        uint32_t rowo = (uint32_t)((m & 127) * 128);
        const float* srow = h_in + (size_t)m * 2048;
#pragma unroll
        for (int i = 0; i < 8; i++) {
            int k = threadIdx.x * 8 + i;
            size_t tb = (mtb + (k >> 6)) * TILE_H;
            uint32_t o = sw128(rowo + (uint32_t)((k & 63) * 2));
            *(__half*)((char*)h_t + tb * 2 + o) = __float2half_rn(srow[k]);
        }
        return;
    }
    b -= PB_H;
    if (b < PB_WQC) { pk_transpose(wqc, wqc_t, C_HID, C_QC, b, 32, 0); return; }
    b -= PB_WQC;
    if (b < PB_WQU) { pk_transpose(wqu, wqu_t, C_QC, C_H * C_D, b, 8, 0); return; }
    b -= PB_WQU;
    if (b < PB_WK)  { pk_transpose(wk, wkv_t, C_HID, C_D, b, 32, 0); return; }
    b -= PB_WK;
    if (b < PB_WV)  { pk_transpose(wv, wkv_t, C_HID, C_D, b, 32, 128); return; }
    b -= PB_WV;
    if (b < PB_W1) {
        int g = b / 1024, tile = b % 1024;
        pk_transpose(w1 + (size_t)g * 512 * 2048,
                     w1_t + (size_t)g * 128 * TILE_H,
                     512, 2048, tile, 8, 0);
        return;
    }
    b -= PB_W1;
    pk_transpose(w2, w2_t, C_G * C_INTER, C_HID, b, 128, 0);
}

// ---------------------------------------------------------------------------
// RoPE + RMSNorm, emitting fp16 swizzled attention tiles directly.
// q warps also fold in 1/sqrt(D) scale. k warps also convert v.
// Tile layout: half index = row*128 + ((chunk ^ (row&7))*8 + (d&7)), chunk=d>>3.
// ---------------------------------------------------------------------------
__device__ __forceinline__ void st_att_half(__half* base, size_t tile, int row, int d, float v) {
    int idx = row * 128 + ((((d >> 3) ^ (row & 7)) << 3) | (d & 7));
    base[tile * 8192 + idx] = __float2half_rn(v);
}

__global__ void __launch_bounds__(256)
rope_kernel(const float* __restrict__ q, const float* __restrict__ kv,
            const float* __restrict__ qw, const float* __restrict__ kw,
            __half* __restrict__ qs, __half* __restrict__ ks, __half* __restrict__ vs) {
    int gid  = blockIdx.x * blockDim.x + threadIdx.x;
    int wid  = gid >> 5;
    int lane = threadIdx.x & 31;

    const float scale = 0.08838834764831845f;
    bool isq = wid < C_TOK * C_H;
    const float* row;
    const float* w;
    int pos, token, h = 0;
    if (isq) {
        token = wid >> 4; h = wid & 15;
        row = q + (size_t)wid * C_D;
        w = qw; pos = token & (C_T - 1);
    } else {
        int wk2 = wid - C_TOK * C_H;
        if (wk2 >= C_TOK) return;
        token = wk2;
        row = kv + (size_t)token * (2 * C_D);
        w = kw; pos = token & (C_T - 1);
    }
    int b = token >> 11;
    int t = token & (C_T - 1);

    float a  = row[lane];
    float b2 = row[lane + 32];
    float c  = row[lane + 64];
    float e  = row[lane + 96];

    double invd = exp(-log(10000.0) * (double)(2 * lane) / 64.0);
    double ang  = (double)pos * invd;
    float cs = (float)cos(ang);
    float sn = (float)sin(ang);

    float r1 = a * cs - b2 * sn;
    float r2 = a * sn + b2 * cs;

    float ss = r1 * r1 + r2 * r2 + c * c + e * e;
#pragma unroll
    for (int off = 16; off; off >>= 1) ss += __shfl_xor_sync(0xffffffffu, ss, off);
    float rms = rsqrtf(ss * (1.0f / 128.0f) + 1e-6f);

    float v0 = r1 * rms * w[lane];
    float v1 = r2 * rms * w[lane + 32];
    float v2 = c  * rms * w[lane + 64];
    float v3 = e  * rms * w[lane + 96];

    int rowi = t & 63;
    if (isq) {
        size_t tile = (size_t)((b * 16 + h) * 32 + (t >> 6));
        st_att_half(qs, tile, rowi, lane,      v0 * scale);
        st_att_half(qs, tile, rowi, lane + 32, v1 * scale);
        st_att_half(qs, tile, rowi, lane + 64, v2 * scale);
        st_att_half(qs, tile, rowi, lane + 96, v3 * scale);
    } else {
        size_t tile = (size_t)(b * 32 + (t >> 6));
        st_att_half(ks, tile, rowi, lane,      v0);
        st_att_half(ks, tile, rowi, lane + 32, v1);
        st_att_half(ks, tile, rowi, lane + 64, v2);
        st_att_half(ks, tile, rowi, lane + 96, v3);
        // v (no rope/norm)
        st_att_half(vs, tile, rowi, lane,      row[128 + lane]);
        st_att_half(vs, tile, rowi, lane + 32, row[160 + lane]);
        st_att_half(vs, tile, rowi, lane + 64, row[192 + lane]);
        st_att_half(vs, tile, rowi, lane + 96, row[224 + lane]);
    }
}

// ---------------------------------------------------------------------------
// fp16 MMA flash attention. CTA per (qtile 64, h, b), 4 warps x 16 q-rows.
// ---------------------------------------------------------------------------
__global__ void __launch_bounds__(128)
attn_kernel(const __half* __restrict__ qs, const __half* __restrict__ ks,
            const __half* __restrict__ vs, const float* __restrict__ sink,
            __half* __restrict__ att_t) {
    constexpr int TB = 16384;
    extern __shared__ __align__(16) char smc[];
    const uint32_t sbase = (uint32_t)__cvta_generic_to_shared(smc);
    const uint32_t mbq  = sbase;
    const uint32_t mbk0 = sbase + 16;
    const uint32_t Qb   = sbase + 1024;
    const uint32_t St   = Qb + TB;

    int qt = blockIdx.x, h = blockIdx.y, b = blockIdx.z;
    int tid = threadIdx.x, warp = tid >> 5, lane = tid & 31;
    int grp = lane >> 2, tig = lane & 3;
    int wr = warp * 16;

    if (tid == 0) { mbar_init(mbq, 1); mbar_init(mbk0, 1); mbar_init(mbk0 + 8, 1); }
    __syncthreads();

    int ktLo = qt > 8 ? qt - 8 : 0;
    int nT = qt - ktLo + 1;

    if (tid == 0) {
        mbar_expect(mbq, TB);
        bulk_g2s(Qb, qs + (size_t)((b * 16 + h) * 32 + qt) * 8192, TB, mbq);
        for (int i = 0; i < 2 && i < nT; i++) {
            uint32_t mb = mbk0 + 8 * i;
            mbar_expect(mb, 2 * TB);
            bulk_g2s(St + i * 2 * TB,      ks + (size_t)(b * 32 + ktLo + i) * 8192, TB, mb);
            bulk_g2s(St + i * 2 * TB + TB, vs + (size_t)(b * 32 + ktLo + i) * 8192, TB, mb);
        }
    }

    float o[16][4];
#pragma unroll
    for (int i = 0; i < 16; i++)
#pragma unroll
        for (int r = 0; r < 4; r++) o[i][r] = 0.f;
    float mA = -1e30f, mB = -1e30f, lA = 0.f, lB = 0.f;

    mbar_wait(mbq, 0);

    const uint32_t axr  = (uint32_t)(lane & 7);
    const uint32_t aBase = Qb + (uint32_t)(wr + (lane & 15)) * 256;
    const uint32_t aSel = (uint32_t)(lane >> 4);
    const int bsrow_off = ((lane >> 4) & 1) * 8 + (lane & 7);
    const uint32_t bsel = (uint32_t)((lane >> 3) & 1);
    const int vrow_off  = ((lane >> 3) & 1) * 8 + (lane & 7);
    const uint32_t vsel = (uint32_t)((lane >> 4) & 1);

    for (int i = 0; i < nT; i++) {
        int kt = ktLo + i;
        mbar_wait(mbk0 + 8 * (i & 1), (uint32_t)((i >> 1) & 1));
        const uint32_t Kb = St + (uint32_t)((i & 1) * 2 * TB);
        const uint32_t Vb = Kb + TB;

        float sc[8][4];
#pragma unroll
        for (int ni = 0; ni < 8; ni++)
#pragma unroll
            for (int r = 0; r < 4; r++) sc[ni][r] = 0.f;

#pragma unroll
        for (int k8 = 0; k8 < 8; k8++) {
            uint32_t a0, a1, a2, a3;
            ldsm4(a0, a1, a2, a3, aBase + (((uint32_t)(2 * k8) + aSel) ^ axr) * 16);
#pragma unroll
            for (int np = 0; np < 4; np++) {
                uint32_t b0, b1, b2, b3;
                uint32_t srow = (uint32_t)(np * 16 + bsrow_off);
                ldsm4(b0, b1, b2, b3,
                      Kb + srow * 256 + (((uint32_t)(2 * k8) + bsel) ^ axr) * 16);
                mma_f16(sc[np*2][0], sc[np*2][1], sc[np*2][2], sc[np*2][3],
                        a0, a1, a2, a3, b0, b1);
                mma_f16(sc[np*2+1][0], sc[np*2+1][1], sc[np*2+1][2], sc[np*2+1][3],
                        a0, a1, a2, a3, b2, b3);
            }
        }

        // mask (edge tiles only)
        if (kt == qt || kt + 8 == qt) {
            int tA2 = qt * 64 + wr + grp;
            int s00 = kt * 64 + tig * 2;
#pragma unroll
            for (int ni = 0; ni < 8; ni++) {
#pragma unroll
                for (int r = 0; r < 4; r++) {
                    int s = s00 + ni * 8 + (r & 1);
                    int t = tA2 + (r >> 1) * 8;
                    if (s > t || s < t - (C_WIN - 1)) sc[ni][r] = -1e30f;
                }
            }
        }

        // online softmax
        float mxA = -1e30f, mxB = -1e30f;
#pragma unroll
        for (int ni = 0; ni < 8; ni++) {
            mxA = fmaxf(mxA, fmaxf(sc[ni][0], sc[ni][1]));
            mxB = fmaxf(mxB, fmaxf(sc[ni][2], sc[ni][3]));
        }
        mxA = fmaxf(mxA, __shfl_xor_sync(0xffffffffu, mxA, 1));
        mxA = fmaxf(mxA, __shfl_xor_sync(0xffffffffu, mxA, 2));
        mxB = fmaxf(mxB, __shfl_xor_sync(0xffffffffu, mxB, 1));
        mxB = fmaxf(mxB, __shfl_xor_sync(0xffffffffu, mxB, 2));
        float nmA = fmaxf(mA, mxA), nmB = fmaxf(mB, mxB);
        float cA = __expf(mA - nmA), cB = __expf(mB - nmB);
        mA = nmA; mB = nmB;
        float sA = 0.f, sB = 0.f;
#pragma unroll
        for (int ni = 0; ni < 8; ni++) {
            sc[ni][0] = __expf(sc[ni][0] - nmA);
            sc[ni][1] = __expf(sc[ni][1] - nmA);
            sc[ni][2] = __expf(sc[ni][2] - nmB);
            sc[ni][3] = __expf(sc[ni][3] - nmB);
            sA += sc[ni][0] + sc[ni][1];
            sB += sc[ni][2] + sc[ni][3];
        }
        sA += __shfl_xor_sync(0xffffffffu, sA, 1);
        sA += __shfl_xor_sync(0xffffffffu, sA, 2);
        sB += __shfl_xor_sync(0xffffffffu, sB, 1);
        sB += __shfl_xor_sync(0xffffffffu, sB, 2);
        lA = lA * cA + sA;
        lB = lB * cB + sB;
#pragma unroll
        for (int nd = 0; nd < 16; nd++) {
            o[nd][0] *= cA; o[nd][1] *= cA;
            o[nd][2] *= cB; o[nd][3] *= cB;
        }

        // P @ V
#pragma unroll
        for (int kp = 0; kp < 4; kp++) {
            __half2 p0 = __floats2half2_rn(sc[2*kp][0],   sc[2*kp][1]);
            __half2 p1 = __floats2half2_rn(sc[2*kp][2],   sc[2*kp][3]);
            __half2 p2 = __floats2half2_rn(sc[2*kp+1][0], sc[2*kp+1][1]);
            __half2 p3 = __floats2half2_rn(sc[2*kp+1][2], sc[2*kp+1][3]);
            uint32_t pa0 = *(uint32_t*)&p0, pa1 = *(uint32_t*)&p1;
            uint32_t pa2 = *(uint32_t*)&p2, pa3 = *(uint32_t*)&p3;
            uint32_t vrow = (uint32_t)(kp * 16 + vrow_off);
#pragma unroll
            for (int dp = 0; dp < 8; dp++) {
                uint32_t b0, b1, b2, b3;
                ldsm4t(b0, b1, b2, b3,
                       Vb + vrow * 256 + (((uint32_t)(2 * dp) + vsel) ^ axr) * 16);
                mma_f16(o[dp*2][0], o[dp*2][1], o[dp*2][2], o[dp*2][3],
                        pa0, pa1, pa2, pa3, b0, b1);
                mma_f16(o[dp*2+1][0], o[dp*2+1][1], o[dp*2+1][2], o[dp*2+1][3],
                        pa0, pa1, pa2, pa3, b2, b3);
            }
        }

        __syncthreads();
        if (tid == 0 && i + 2 < nT) {
            uint32_t mb = mbk0 + 8 * (i & 1);
            mbar_expect(mb, 2 * TB);
            bulk_g2s(St + (i & 1) * 2 * TB,      ks + (size_t)(b * 32 + kt + 2) * 8192, TB, mb);
            bulk_g2s(St + (i & 1) * 2 * TB + TB, vs + (size_t)(b * 32 + kt + 2) * 8192, TB, mb);
        }
    }

    // sink + normalize
    float sl = sink[h];
    float nmA = fmaxf(mA, sl);
    float fA  = __expf(mA - nmA);
    float dA  = lA * fA + __expf(sl - nmA);
    float scAf = fA / dA;
    float nmB = fmaxf(mB, sl);
    float fB  = __expf(mB - nmB);
    float dB  = lB * fB + __expf(sl - nmB);
    float scBf = fB / dB;

    int tokenA = b * C_T + qt * 64 + wr + grp;
    int tokenB = tokenA + 8;
#pragma unroll
    for (int nd = 0; nd < 16; nd++) {
        int col = h * 128 + nd * 8 + tig * 2;
        {
            size_t tb = ((size_t)(tokenA >> 7) * 32 + (col >> 6)) * TILE_H;
            uint32_t off = sw128((uint32_t)((tokenA & 127) * 128 + (col & 63) * 2));
            __half2 hv = __floats2half2_rn(o[nd][0] * scAf, o[nd][1] * scAf);
            *(__half2*)((char*)att_t + tb * 2 + off) = hv;
        }
        {
            size_t tb = ((size_t)(tokenB >> 7) * 32 + (col >> 6)) * TILE_H;
            uint32_t off = sw128((uint32_t)((tokenB & 127) * 128 + (col & 63) * 2));
            __half2 hv = __floats2half2_rn(o[nd][2] * scBf, o[nd][3] * scBf);
            *(__half2*)((char*)att_t + tb * 2 + off) = hv;
        }
    }
}

// ---------------------------------------------------------------------------
extern "C" void kernel_launch(void* const* d_in, const int* in_sizes, int n_in,
                              void* d_out, int out_size) {
    const float* h_in     = (const float*)d_in[0];
    const float* wq_comp  = (const float*)d_in[1];
    const float* wq_up    = (const float*)d_in[2];
    const float* wk       = (const float*)d_in[3];
    const float* wv       = (const float*)d_in[4];
    const float* q_norm_w = (const float*)d_in[5];
    const float* k_norm_w = (const float*)d_in[6];
    const float* sink     = (const float*)d_in[7];
    const float* out_w1   = (const float*)d_in[8];
    const float* out_w2   = (const float*)d_in[9];
    float* out = (float*)d_out;

    __half *h_t, *hc_t, *att_t, *y1_t, *wqc_t, *wqu_t, *wkv_t, *w1_t, *w2_t, *qsp, *ksp, *vsp;
    float *q, *kv;
    cudaGetSymbolAddress((void**)&h_t,   g_h_t);
    cudaGetSymbolAddress((void**)&hc_t,  g_hc_t);
    cudaGetSymbolAddress((void**)&att_t, g_att_t);
    cudaGetSymbolAddress((void**)&y1_t,  g_y1_t);
    cudaGetSymbolAddress((void**)&wqc_t, g_wqc_t);
    cudaGetSymbolAddress((void**)&wqu_t, g_wqu_t);
    cudaGetSymbolAddress((void**)&wkv_t, g_wkv_t);
    cudaGetSymbolAddress((void**)&w1_t,  g_w1_t);
    cudaGetSymbolAddress((void**)&w2_t,  g_w2_t);
    cudaGetSymbolAddress((void**)&q,     g_q);
    cudaGetSymbolAddress((void**)&kv,    g_kv);
    cudaGetSymbolAddress((void**)&qsp,   g_qs);
    cudaGetSymbolAddress((void**)&ksp,   g_ks);
    cudaGetSymbolAddress((void**)&vsp,   g_vs);

    constexpr int SM_TMA  = 1024 + 3 * 32768;            // 99328 B (2 CTAs/SM)
    constexpr int SM_ATTN = 1024 + 16384 + 2 * 32768;    // 82944 B
    cudaFuncSetAttribute(gemm_tma<0>, cudaFuncAttributeMaxDynamicSharedMemorySize, SM_TMA);
    cudaFuncSetAttribute(gemm_tma<1>, cudaFuncAttributeMaxDynamicSharedMemorySize, SM_TMA);
    cudaFuncSetAttribute(attn_kernel, cudaFuncAttributeMaxDynamicSharedMemorySize, SM_ATTN);

    // [0] pack
    pack_kernel<<<PB_TOTAL, 256>>>(h_in, h_t, wq_comp, wqc_t, wq_up, wqu_t,
                                   wk, wv, wkv_t, out_w1, w1_t, out_w2, w2_t);

    // [1] hc = h @ wq_comp  -> half tiled (KT=32)
    gemm_tma<1><<<dim3(4, 32), 512, SM_TMA>>>(
        h_t, wqc_t, nullptr, hc_t, 32, 32, 32, 0, 0, 8, 0);

    // [2] q = hc @ wq_up    -> fp32 (KT=8)
    gemm_tma<0><<<dim3(16, 32), 512, SM_TMA>>>(
        hc_t, wqu_t, q, nullptr, 8, 8, 8, 0, 0, C_H * C_D, 0);

    // [3] kv = h @ wkv      -> fp32 (KT=32)
    gemm_tma<0><<<dim3(2, 32), 512, SM_TMA>>>(
        h_t, wkv_t, kv, nullptr, 32, 32, 32, 0, 0, 2 * C_D, 0);

    // [4] RoPE + RMSNorm -> fp16 swizzled q/k/v tiles
    {
        int warps = C_TOK * C_H + C_TOK;
        rope_kernel<<<(warps * 32 + 255) / 256, 256>>>(q, kv, q_norm_w, k_norm_w,
                                                       qsp, ksp, vsp);
    }

    // [5] flash attention -> att half tiled (profiled launch)
    attn_kernel<<<dim3(32, 16, 2), 128, SM_ATTN>>>(qsp, ksp, vsp, sink, att_t);

    // [6] y1 = grouped att @ w1 -> half tiled (KT=8)
    gemm_tma<1><<<dim3(16, 32, C_G), 512, SM_TMA>>>(
        att_t, w1_t, nullptr, y1_t, 8, 32, 8, 8, 128, 128, 32);

    // [7] out = y1 @ out_w2 -> fp32 (KT=128)
    gemm_tma<0><<<dim3(16, 32), 512, SM_TMA>>>(
        y1_t, w2_t, out, nullptr, 128, 128, 128, 0, 0, C_HID, 0);
}

// round 13
// speedup vs baseline: 4.2982x; 1.0512x over previous
#include <cuda_runtime.h>
#include <cuda_fp16.h>
#include <math.h>
#include <stdint.h>

// Problem constants
constexpr int C_B    = 2;
constexpr int C_T    = 2048;
constexpr int C_HID  = 2048;
constexpr int C_H    = 16;
constexpr int C_D    = 128;
constexpr int C_WIN  = 512;
constexpr int C_QC   = 512;
constexpr int C_G    = 4;
constexpr int C_INTER= 2048;
constexpr int C_TOK  = C_B * C_T;
constexpr int TILE_H = 8192;            // halves per 16KB GEMM tile [128 x 64]

// ---------------------------------------------------------------------------
// Scratch
// ---------------------------------------------------------------------------
__device__ __align__(1024) __half g_h_t  [(size_t)32 * 32 * TILE_H];
__device__ __align__(1024) __half g_hc_t [(size_t)32 * 8  * TILE_H];
__device__ __align__(1024) __half g_att_t[(size_t)32 * 32 * TILE_H];
__device__ __align__(1024) __half g_y1_t [(size_t)32 * 128* TILE_H];
__device__ __align__(1024) __half g_wqc_t[(size_t)4  * 32 * TILE_H];
__device__ __align__(1024) __half g_wqu_t[(size_t)16 * 8  * TILE_H];
__device__ __align__(1024) __half g_wkv_t[(size_t)2  * 32 * TILE_H];
__device__ __align__(1024) __half g_w1_t [(size_t)4 * 16 * 8 * TILE_H];
__device__ __align__(1024) __half g_w2_t [(size_t)16 * 128* TILE_H];
__device__ float g_q [C_TOK * C_H * C_D];
__device__ float g_kv[C_TOK * 2 * C_D];
// Attention tiles: [64 rows x 256B] fp16, chunk-swizzled (chunk ^ (row&7))
__device__ __align__(1024) __half g_qs[(size_t)C_B * C_H * 32 * 8192];  // scaled q
__device__ __align__(1024) __half g_ks[(size_t)C_B * 32 * 8192];
__device__ __align__(1024) __half g_vs[(size_t)C_B * 32 * 8192];

// ---------------------------------------------------------------------------
__device__ __forceinline__ uint32_t sw128(uint32_t off) {
    return off ^ ((off >> 3) & 0x70);
}

__device__ __forceinline__ void mma_f16(float& c0, float& c1, float& c2, float& c3,
                                        uint32_t a0, uint32_t a1, uint32_t a2, uint32_t a3,
                                        uint32_t b0, uint32_t b1) {
    asm volatile(
        "mma.sync.aligned.m16n8k16.row.col.f32.f16.f16.f32 "
        "{%0,%1,%2,%3}, {%4,%5,%6,%7}, {%8,%9}, {%0,%1,%2,%3};"
        : "+f"(c0), "+f"(c1), "+f"(c2), "+f"(c3)
        : "r"(a0), "r"(a1), "r"(a2), "r"(a3), "r"(b0), "r"(b1));
}

__device__ __forceinline__ void ldsm4(uint32_t& r0, uint32_t& r1, uint32_t& r2, uint32_t& r3,
                                      uint32_t addr) {
    asm volatile("ldmatrix.sync.aligned.m8n8.x4.shared.b16 {%0,%1,%2,%3}, [%4];"
                 : "=r"(r0), "=r"(r1), "=r"(r2), "=r"(r3) : "r"(addr));
}
__device__ __forceinline__ void ldsm4t(uint32_t& r0, uint32_t& r1, uint32_t& r2, uint32_t& r3,
                                       uint32_t addr) {
    asm volatile("ldmatrix.sync.aligned.m8n8.x4.trans.shared.b16 {%0,%1,%2,%3}, [%4];"
                 : "=r"(r0), "=r"(r1), "=r"(r2), "=r"(r3) : "r"(addr));
}

__device__ __forceinline__ void mbar_init(uint32_t a, uint32_t cnt) {
    asm volatile("mbarrier.init.shared.b64 [%0], %1;" :: "r"(a), "r"(cnt) : "memory");
}
__device__ __forceinline__ void mbar_expect(uint32_t a, uint32_t bytes) {
    asm volatile("mbarrier.arrive.expect_tx.shared.b64 _, [%0], %1;"
                 :: "r"(a), "r"(bytes) : "memory");
}
__device__ __forceinline__ void mbar_wait(uint32_t a, uint32_t parity) {
    uint32_t done;
    asm volatile(
        "{\n\t.reg .pred p;\n\t"
        "mbarrier.try_wait.parity.acquire.cta.shared::cta.b64 p, [%1], %2;\n\t"
        "selp.b32 %0, 1, 0, p;\n\t}"
        : "=r"(done) : "r"(a), "r"(parity) : "memory");
    if (!done) {
        asm volatile(
            "{\n\t.reg .pred P1;\n\t"
            "WAIT_LOOP_%=:\n\t"
            "mbarrier.try_wait.parity.acquire.cta.shared::cta.b64 P1, [%0], %1, 0x989680;\n\t"
            "@P1 bra.uni WAIT_DONE_%=;\n\t"
            "bra.uni WAIT_LOOP_%=;\n\t"
            "WAIT_DONE_%=:\n\t}"
            :: "r"(a), "r"(parity) : "memory");
    }
}
__device__ __forceinline__ void bulk_g2s(uint32_t dst, const void* src, uint32_t bytes,
                                         uint32_t mbar) {
    asm volatile(
        "cp.async.bulk.shared::cta.global.mbarrier::complete_tx::bytes [%0], [%1], %2, [%3];"
        :: "r"(dst), "l"(src), "r"(bytes), "r"(mbar) : "memory");
}

// ---------------------------------------------------------------------------
// TMA-fed fp16 GEMM. 256 threads, 8 warps (4m x 2n), warp tile 32x64.
// S=3 stages, 2 CTAs/SM.
// ---------------------------------------------------------------------------
template<int EPI>
__global__ void __launch_bounds__(256, 2)
gemm_tma(const __half* __restrict__ A, const __half* __restrict__ B,
         float* __restrict__ Cf, __half* __restrict__ Ch,
         int KT, int ldaT, int ldbT, int azA, int azB, int ldcP, int azC) {
    constexpr int S = 3;
    constexpr int STAGEB = 2 * 16384;

    extern __shared__ __align__(16) char smc[];
    const uint32_t sbase = (uint32_t)__cvta_generic_to_shared(smc);
    const uint32_t mb0   = sbase;
    const uint32_t data0 = sbase + 1024;

    const int tid  = threadIdx.x;
    const int warp = tid >> 5;
    const int lane = tid & 31;
    const int wm   = (warp >> 1) * 32;   // 4 m-warps
    const int wn   = (warp & 1) * 64;    // 2 n-warps
    const int grp  = lane >> 2;
    const int tig  = lane & 3;

    const __half* Abase = A + ((size_t)blockIdx.y * ldaT + (size_t)blockIdx.z * azA) * TILE_H;
    const __half* Bbase = B + ((size_t)blockIdx.x * ldbT + (size_t)blockIdx.z * azB) * TILE_H;

    if (tid == 0) {
        for (int s = 0; s < S; s++) mbar_init(mb0 + 8 * s, 1);
    }
    __syncthreads();
    if (tid == 0) {
        for (int i = 0; i < S - 1 && i < KT; i++) {
            uint32_t mb = mb0 + 8 * i;
            mbar_expect(mb, 32768);
            bulk_g2s(data0 + i * STAGEB,         Abase + (size_t)i * TILE_H, 16384, mb);
            bulk_g2s(data0 + i * STAGEB + 16384, Bbase + (size_t)i * TILE_H, 16384, mb);
        }
    }

    float acc[2][8][4];
#pragma unroll
    for (int i = 0; i < 2; i++)
#pragma unroll
        for (int j = 0; j < 8; j++)
#pragma unroll
            for (int r = 0; r < 4; r++) acc[i][j][r] = 0.f;

    const int aRow = wm + (lane & 15);
    const uint32_t aOff = (uint32_t)((lane >> 4) * 16);
    const uint32_t aXor = (uint32_t)((aRow & 7) << 4);
    const uint32_t aB0  = (uint32_t)(aRow * 128);
    const int bRow = wn + ((lane >> 4) & 1) * 8 + (lane & 7);
    const uint32_t bOff = (uint32_t)(((lane >> 3) & 1) * 16);
    const uint32_t bXor = (uint32_t)((lane & 7) << 4);
    const uint32_t bB0  = (uint32_t)(bRow * 128);

    for (int kt = 0; kt < KT; kt++) {
        mbar_wait(mb0 + 8 * (kt % S), (uint32_t)((kt / S) & 1));
        if (tid == 0) {
            int j = kt + S - 1;
            if (j < KT) {
                uint32_t mb = mb0 + 8 * (j % S);
                uint32_t st = data0 + (j % S) * STAGEB;
                mbar_expect(mb, 32768);
                bulk_g2s(st,         Abase + (size_t)j * TILE_H, 16384, mb);
                bulk_g2s(st + 16384, Bbase + (size_t)j * TILE_H, 16384, mb);
            }
        }
        const uint32_t stb = data0 + (kt % S) * STAGEB;
        const uint32_t aT = stb + aB0;
        const uint32_t bT = stb + 16384 + bB0;
#pragma unroll
        for (int ks = 0; ks < 4; ks++) {
            const uint32_t ak = ((uint32_t)(ks * 32) + aOff) ^ aXor;
            const uint32_t bk = ((uint32_t)(ks * 32) + bOff) ^ bXor;
            uint32_t ah[2][4], bh[4][4];
            ldsm4(ah[0][0], ah[0][1], ah[0][2], ah[0][3], aT + ak);
            ldsm4(ah[1][0], ah[1][1], ah[1][2], ah[1][3], aT + 16 * 128 + ak);
#pragma unroll
            for (int p = 0; p < 4; p++)
                ldsm4(bh[p][0], bh[p][1], bh[p][2], bh[p][3], bT + p * (16 * 128) + bk);
#pragma unroll
            for (int mi = 0; mi < 2; mi++)
#pragma unroll
                for (int ni = 0; ni < 8; ni++) {
                    const int p = ni >> 1, q = (ni & 1) * 2;
                    mma_f16(acc[mi][ni][0], acc[mi][ni][1], acc[mi][ni][2], acc[mi][ni][3],
                            ah[mi][0], ah[mi][1], ah[mi][2], ah[mi][3],
                            bh[p][q], bh[p][q + 1]);
                }
        }
        __syncthreads();
    }

#pragma unroll
    for (int mi = 0; mi < 2; mi++) {
#pragma unroll
        for (int ni = 0; ni < 8; ni++) {
#pragma unroll
            for (int half_ = 0; half_ < 2; half_++) {
                float v0 = acc[mi][ni][half_ * 2], v1 = acc[mi][ni][half_ * 2 + 1];
                int mrow = wm + mi * 16 + grp + half_ * 8;
                int kcol = wn + ni * 8 + tig * 2;
                if (EPI == 0) {
                    size_t off = (size_t)(blockIdx.y * 128 + mrow) * ldcP
                               + blockIdx.x * 128 + kcol;
                    *(float2*)(Cf + off) = make_float2(v0, v1);
                } else {
                    int ktile = blockIdx.x * 2 + (kcol >> 6) + blockIdx.z * azC;
                    size_t tb = ((size_t)blockIdx.y * ldcP + ktile) * TILE_H;
                    uint32_t o = sw128((uint32_t)(mrow * 128 + (kcol & 63) * 2));
                    __half2 hv;
                    hv.x = __float2half_rn(v0);
                    hv.y = __float2half_rn(v1);
                    *(__half2*)((char*)Ch + tb * 2 + o) = hv;
                }
            }
        }
    }
}

// ---------------------------------------------------------------------------
// Pack megakernel (unchanged)
// ---------------------------------------------------------------------------
constexpr int PB_H   = 4096;
constexpr int PB_WQC = 1024;
constexpr int PB_WQU = 1024;
constexpr int PB_WK  = 256;
constexpr int PB_WV  = 256;
constexpr int PB_W1  = 4096;
constexpr int PB_W2  = 16384;
constexpr int PB_TOTAL = PB_H + PB_WQC + PB_WQU + PB_WK + PB_WV + PB_W1 + PB_W2;

__device__ __forceinline__ void pk_transpose(const float* __restrict__ src,
                                             __half* __restrict__ dst,
                                             int K, int N, int tile, int KTt, int nBase) {
    __shared__ float t[32][33];
    int tx = threadIdx.x & 31, ty = threadIdx.x >> 5;
    int ntx = N / 32;
    int n0 = (tile % ntx) * 32, k0 = (tile / ntx) * 32;
#pragma unroll
    for (int i = ty; i < 32; i += 8)
        t[i][tx] = src[(size_t)(k0 + i) * N + n0 + tx];
    __syncthreads();
#pragma unroll
    for (int i = ty; i < 32; i += 8) {
        int n = nBase + n0 + i;
        int k = k0 + tx;
        size_t tb = ((size_t)(n >> 7) * KTt + (k >> 6)) * TILE_H;
        uint32_t o = sw128((uint32_t)((n & 127) * 128 + (k & 63) * 2));
        *(__half*)((char*)dst + tb * 2 + o) = __float2half_rn(t[tx][i]);
    }
}

__global__ void __launch_bounds__(256)
pack_kernel(const float* __restrict__ h_in, __half* __restrict__ h_t,
            const float* __restrict__ wqc, __half* __restrict__ wqc_t,
            const float* __restrict__ wqu, __half* __restrict__ wqu_t,
            const float* __restrict__ wk,  const float* __restrict__ wv,
            __half* __restrict__ wkv_t,
            const float* __restrict__ w1,  __half* __restrict__ w1_t,
            const float* __restrict__ w2,  __half* __restrict__ w2_t) {
    int b = blockIdx.x;
    if (b < PB_H) {
        int m = b;
        size_t mtb = (size_t)(m >> 7) * 32;
        uint32_t rowo = (uint32_t)((m & 127) * 128);
        const float* srow = h_in + (size_t)m * 2048;
#pragma unroll
        for (int i = 0; i < 8; i++) {
            int k = threadIdx.x * 8 + i;
            size_t tb = (mtb + (k >> 6)) * TILE_H;
            uint32_t o = sw128(rowo + (uint32_t)((k & 63) * 2));
            *(__half*)((char*)h_t + tb * 2 + o) = __float2half_rn(srow[k]);
        }
        return;
    }
    b -= PB_H;
    if (b < PB_WQC) { pk_transpose(wqc, wqc_t, C_HID, C_QC, b, 32, 0); return; }
    b -= PB_WQC;
    if (b < PB_WQU) { pk_transpose(wqu, wqu_t, C_QC, C_H * C_D, b, 8, 0); return; }
    b -= PB_WQU;
    if (b < PB_WK)  { pk_transpose(wk, wkv_t, C_HID, C_D, b, 32, 0); return; }
    b -= PB_WK;
    if (b < PB_WV)  { pk_transpose(wv, wkv_t, C_HID, C_D, b, 32, 128); return; }
    b -= PB_WV;
    if (b < PB_W1) {
        int g = b / 1024, tile = b % 1024;
        pk_transpose(w1 + (size_t)g * 512 * 2048,
                     w1_t + (size_t)g * 128 * TILE_H,
                     512, 2048, tile, 8, 0);
        return;
    }
    b -= PB_W1;
    pk_transpose(w2, w2_t, C_G * C_INTER, C_HID, b, 128, 0);
}

// ---------------------------------------------------------------------------
// RoPE + RMSNorm, emitting fp16 swizzled attention tiles directly.
// ---------------------------------------------------------------------------
__device__ __forceinline__ void st_att_half(__half* base, size_t tile, int row, int d, float v) {
    int idx = row * 128 + ((((d >> 3) ^ (row & 7)) << 3) | (d & 7));
    base[tile * 8192 + idx] = __float2half_rn(v);
}

__global__ void __launch_bounds__(256)
rope_kernel(const float* __restrict__ q, const float* __restrict__ kv,
            const float* __restrict__ qw, const float* __restrict__ kw,
            __half* __restrict__ qs, __half* __restrict__ ks, __half* __restrict__ vs) {
    int gid  = blockIdx.x * blockDim.x + threadIdx.x;
    int wid  = gid >> 5;
    int lane = threadIdx.x & 31;

    const float scale = 0.08838834764831845f;
    bool isq = wid < C_TOK * C_H;
    const float* row;
    const float* w;
    int pos, token, h = 0;
    if (isq) {
        token = wid >> 4; h = wid & 15;
        row = q + (size_t)wid * C_D;
        w = qw; pos = token & (C_T - 1);
    } else {
        int wk2 = wid - C_TOK * C_H;
        if (wk2 >= C_TOK) return;
        token = wk2;
        row = kv + (size_t)token * (2 * C_D);
        w = kw; pos = token & (C_T - 1);
    }
    int b = token >> 11;
    int t = token & (C_T - 1);

    float a  = row[lane];
    float b2 = row[lane + 32];
    float c  = row[lane + 64];
    float e  = row[lane + 96];

    double invd = exp(-log(10000.0) * (double)(2 * lane) / 64.0);
    double ang  = (double)pos * invd;
    float cs = (float)cos(ang);
    float sn = (float)sin(ang);

    float r1 = a * cs - b2 * sn;
    float r2 = a * sn + b2 * cs;

    float ss = r1 * r1 + r2 * r2 + c * c + e * e;
#pragma unroll
    for (int off = 16; off; off >>= 1) ss += __shfl_xor_sync(0xffffffffu, ss, off);
    float rms = rsqrtf(ss * (1.0f / 128.0f) + 1e-6f);

    float v0 = r1 * rms * w[lane];
    float v1 = r2 * rms * w[lane + 32];
    float v2 = c  * rms * w[lane + 64];
    float v3 = e  * rms * w[lane + 96];

    int rowi = t & 63;
    if (isq) {
        size_t tile = (size_t)((b * 16 + h) * 32 + (t >> 6));
        st_att_half(qs, tile, rowi, lane,      v0 * scale);
        st_att_half(qs, tile, rowi, lane + 32, v1 * scale);
        st_att_half(qs, tile, rowi, lane + 64, v2 * scale);
        st_att_half(qs, tile, rowi, lane + 96, v3 * scale);
    } else {
        size_t tile = (size_t)(b * 32 + (t >> 6));
        st_att_half(ks, tile, rowi, lane,      v0);
        st_att_half(ks, tile, rowi, lane + 32, v1);
        st_att_half(ks, tile, rowi, lane + 64, v2);
        st_att_half(ks, tile, rowi, lane + 96, v3);
        st_att_half(vs, tile, rowi, lane,      row[128 + lane]);
        st_att_half(vs, tile, rowi, lane + 32, row[160 + lane]);
        st_att_half(vs, tile, rowi, lane + 64, row[192 + lane]);
        st_att_half(vs, tile, rowi, lane + 96, row[224 + lane]);
    }
}

// ---------------------------------------------------------------------------
// fp16 MMA flash attention (unchanged from R12).
// ---------------------------------------------------------------------------
__global__ void __launch_bounds__(128)
attn_kernel(const __half* __restrict__ qs, const __half* __restrict__ ks,
            const __half* __restrict__ vs, const float* __restrict__ sink,
            __half* __restrict__ att_t) {
    constexpr int TB = 16384;
    extern __shared__ __align__(16) char smc[];
    const uint32_t sbase = (uint32_t)__cvta_generic_to_shared(smc);
    const uint32_t mbq  = sbase;
    const uint32_t mbk0 = sbase + 16;
    const uint32_t Qb   = sbase + 1024;
    const uint32_t St   = Qb + TB;

    int qt = blockIdx.x, h = blockIdx.y, b = blockIdx.z;
    int tid = threadIdx.x, warp = tid >> 5, lane = tid & 31;
    int grp = lane >> 2, tig = lane & 3;
    int wr = warp * 16;

    if (tid == 0) { mbar_init(mbq, 1); mbar_init(mbk0, 1); mbar_init(mbk0 + 8, 1); }
    __syncthreads();

    int ktLo = qt > 8 ? qt - 8 : 0;
    int nT = qt - ktLo + 1;

    if (tid == 0) {
        mbar_expect(mbq, TB);
        bulk_g2s(Qb, qs + (size_t)((b * 16 + h) * 32 + qt) * 8192, TB, mbq);
        for (int i = 0; i < 2 && i < nT; i++) {
            uint32_t mb = mbk0 + 8 * i;
            mbar_expect(mb, 2 * TB);
            bulk_g2s(St + i * 2 * TB,      ks + (size_t)(b * 32 + ktLo + i) * 8192, TB, mb);
            bulk_g2s(St + i * 2 * TB + TB, vs + (size_t)(b * 32 + ktLo + i) * 8192, TB, mb);
        }
    }

    float o[16][4];
#pragma unroll
    for (int i = 0; i < 16; i++)
#pragma unroll
        for (int r = 0; r < 4; r++) o[i][r] = 0.f;
    float mA = -1e30f, mB = -1e30f, lA = 0.f, lB = 0.f;

    mbar_wait(mbq, 0);

    const uint32_t axr  = (uint32_t)(lane & 7);
    const uint32_t aBase = Qb + (uint32_t)(wr + (lane & 15)) * 256;
    const uint32_t aSel = (uint32_t)(lane >> 4);
    const int bsrow_off = ((lane >> 4) & 1) * 8 + (lane & 7);
    const uint32_t bsel = (uint32_t)((lane >> 3) & 1);
    const int vrow_off  = ((lane >> 3) & 1) * 8 + (lane & 7);
    const uint32_t vsel = (uint32_t)((lane >> 4) & 1);

    for (int i = 0; i < nT; i++) {
        int kt = ktLo + i;
        mbar_wait(mbk0 + 8 * (i & 1), (uint32_t)((i >> 1) & 1));
        const uint32_t Kb = St + (uint32_t)((i & 1) * 2 * TB);
        const uint32_t Vb = Kb + TB;

        float sc[8][4];
#pragma unroll
        for (int ni = 0; ni < 8; ni++)
#pragma unroll
            for (int r = 0; r < 4; r++) sc[ni][r] = 0.f;

#pragma unroll
        for (int k8 = 0; k8 < 8; k8++) {
            uint32_t a0, a1, a2, a3;
            ldsm4(a0, a1, a2, a3, aBase + (((uint32_t)(2 * k8) + aSel) ^ axr) * 16);
#pragma unroll
            for (int np = 0; np < 4; np++) {
                uint32_t b0, b1, b2, b3;
                uint32_t srow = (uint32_t)(np * 16 + bsrow_off);
                ldsm4(b0, b1, b2, b3,
                      Kb + srow * 256 + (((uint32_t)(2 * k8) + bsel) ^ axr) * 16);
                mma_f16(sc[np*2][0], sc[np*2][1], sc[np*2][2], sc[np*2][3],
                        a0, a1, a2, a3, b0, b1);
                mma_f16(sc[np*2+1][0], sc[np*2+1][1], sc[np*2+1][2], sc[np*2+1][3],
                        a0, a1, a2, a3, b2, b3);
            }
        }

        if (kt == qt || kt + 8 == qt) {
            int tA2 = qt * 64 + wr + grp;
            int s00 = kt * 64 + tig * 2;
#pragma unroll
            for (int ni = 0; ni < 8; ni++) {
#pragma unroll
                for (int r = 0; r < 4; r++) {
                    int s = s00 + ni * 8 + (r & 1);
                    int t = tA2 + (r >> 1) * 8;
                    if (s > t || s < t - (C_WIN - 1)) sc[ni][r] = -1e30f;
                }
            }
        }

        float mxA = -1e30f, mxB = -1e30f;
#pragma unroll
        for (int ni = 0; ni < 8; ni++) {
            mxA = fmaxf(mxA, fmaxf(sc[ni][0], sc[ni][1]));
            mxB = fmaxf(mxB, fmaxf(sc[ni][2], sc[ni][3]));
        }
        mxA = fmaxf(mxA, __shfl_xor_sync(0xffffffffu, mxA, 1));
        mxA = fmaxf(mxA, __shfl_xor_sync(0xffffffffu, mxA, 2));
        mxB = fmaxf(mxB, __shfl_xor_sync(0xffffffffu, mxB, 1));
        mxB = fmaxf(mxB, __shfl_xor_sync(0xffffffffu, mxB, 2));
        float nmA = fmaxf(mA, mxA), nmB = fmaxf(mB, mxB);
        float cA = __expf(mA - nmA), cB = __expf(mB - nmB);
        mA = nmA; mB = nmB;
        float sA = 0.f, sB = 0.f;
#pragma unroll
        for (int ni = 0; ni < 8; ni++) {
            sc[ni][0] = __expf(sc[ni][0] - nmA);
            sc[ni][1] = __expf(sc[ni][1] - nmA);
            sc[ni][2] = __expf(sc[ni][2] - nmB);
            sc[ni][3] = __expf(sc[ni][3] - nmB);
            sA += sc[ni][0] + sc[ni][1];
            sB += sc[ni][2] + sc[ni][3];
        }
        sA += __shfl_xor_sync(0xffffffffu, sA, 1);
        sA += __shfl_xor_sync(0xffffffffu, sA, 2);
        sB += __shfl_xor_sync(0xffffffffu, sB, 1);
        sB += __shfl_xor_sync(0xffffffffu, sB, 2);
        lA = lA * cA + sA;
        lB = lB * cB + sB;
#pragma unroll
        for (int nd = 0; nd < 16; nd++) {
            o[nd][0] *= cA; o[nd][1] *= cA;
            o[nd][2] *= cB; o[nd][3] *= cB;
        }

#pragma unroll
        for (int kp = 0; kp < 4; kp++) {
            __half2 p0 = __floats2half2_rn(sc[2*kp][0],   sc[2*kp][1]);
            __half2 p1 = __floats2half2_rn(sc[2*kp][2],   sc[2*kp][3]);
            __half2 p2 = __floats2half2_rn(sc[2*kp+1][0], sc[2*kp+1][1]);
            __half2 p3 = __floats2half2_rn(sc[2*kp+1][2], sc[2*kp+1][3]);
            uint32_t pa0 = *(uint32_t*)&p0, pa1 = *(uint32_t*)&p1;
            uint32_t pa2 = *(uint32_t*)&p2, pa3 = *(uint32_t*)&p3;
            uint32_t vrow = (uint32_t)(kp * 16 + vrow_off);
#pragma unroll
            for (int dp = 0; dp < 8; dp++) {
                uint32_t b0, b1, b2, b3;
                ldsm4t(b0, b1, b2, b3,
                       Vb + vrow * 256 + (((uint32_t)(2 * dp) + vsel) ^ axr) * 16);
                mma_f16(o[dp*2][0], o[dp*2][1], o[dp*2][2], o[dp*2][3],
                        pa0, pa1, pa2, pa3, b0, b1);
                mma_f16(o[dp*2+1][0], o[dp*2+1][1], o[dp*2+1][2], o[dp*2+1][3],
                        pa0, pa1, pa2, pa3, b2, b3);
            }
        }

        __syncthreads();
        if (tid == 0 && i + 2 < nT) {
            uint32_t mb = mbk0 + 8 * (i & 1);
            mbar_expect(mb, 2 * TB);
            bulk_g2s(St + (i & 1) * 2 * TB,      ks + (size_t)(b * 32 + kt + 2) * 8192, TB, mb);
            bulk_g2s(St + (i & 1) * 2 * TB + TB, vs + (size_t)(b * 32 + kt + 2) * 8192, TB, mb);
        }
    }

    float sl = sink[h];
    float nmA = fmaxf(mA, sl);
    float fA  = __expf(mA - nmA);
    float dA  = lA * fA + __expf(sl - nmA);
    float scAf = fA / dA;
    float nmB = fmaxf(mB, sl);
    float fB  = __expf(mB - nmB);
    float dB  = lB * fB + __expf(sl - nmB);
    float scBf = fB / dB;

    int tokenA = b * C_T + qt * 64 + wr + grp;
    int tokenB = tokenA + 8;
#pragma unroll
    for (int nd = 0; nd < 16; nd++) {
        int col = h * 128 + nd * 8 + tig * 2;
        {
            size_t tb = ((size_t)(tokenA >> 7) * 32 + (col >> 6)) * TILE_H;
            uint32_t off = sw128((uint32_t)((tokenA & 127) * 128 + (col & 63) * 2));
            __half2 hv = __floats2half2_rn(o[nd][0] * scAf, o[nd][1] * scAf);
            *(__half2*)((char*)att_t + tb * 2 + off) = hv;
        }
        {
            size_t tb = ((size_t)(tokenB >> 7) * 32 + (col >> 6)) * TILE_H;
            uint32_t off = sw128((uint32_t)((tokenB & 127) * 128 + (col & 63) * 2));
            __half2 hv = __floats2half2_rn(o[nd][2] * scBf, o[nd][3] * scBf);
            *(__half2*)((char*)att_t + tb * 2 + off) = hv;
        }
    }
}

// ---------------------------------------------------------------------------
extern "C" void kernel_launch(void* const* d_in, const int* in_sizes, int n_in,
                              void* d_out, int out_size) {
    const float* h_in     = (const float*)d_in[0];
    const float* wq_comp  = (const float*)d_in[1];
    const float* wq_up    = (const float*)d_in[2];
    const float* wk       = (const float*)d_in[3];
    const float* wv       = (const float*)d_in[4];
    const float* q_norm_w = (const float*)d_in[5];
    const float* k_norm_w = (const float*)d_in[6];
    const float* sink     = (const float*)d_in[7];
    const float* out_w1   = (const float*)d_in[8];
    const float* out_w2   = (const float*)d_in[9];
    float* out = (float*)d_out;

    __half *h_t, *hc_t, *att_t, *y1_t, *wqc_t, *wqu_t, *wkv_t, *w1_t, *w2_t, *qsp, *ksp, *vsp;
    float *q, *kv;
    cudaGetSymbolAddress((void**)&h_t,   g_h_t);
    cudaGetSymbolAddress((void**)&hc_t,  g_hc_t);
    cudaGetSymbolAddress((void**)&att_t, g_att_t);
    cudaGetSymbolAddress((void**)&y1_t,  g_y1_t);
    cudaGetSymbolAddress((void**)&wqc_t, g_wqc_t);
    cudaGetSymbolAddress((void**)&wqu_t, g_wqu_t);
    cudaGetSymbolAddress((void**)&wkv_t, g_wkv_t);
    cudaGetSymbolAddress((void**)&w1_t,  g_w1_t);
    cudaGetSymbolAddress((void**)&w2_t,  g_w2_t);
    cudaGetSymbolAddress((void**)&q,     g_q);
    cudaGetSymbolAddress((void**)&kv,    g_kv);
    cudaGetSymbolAddress((void**)&qsp,   g_qs);
    cudaGetSymbolAddress((void**)&ksp,   g_ks);
    cudaGetSymbolAddress((void**)&vsp,   g_vs);

    constexpr int SM_TMA  = 1024 + 3 * 32768;            // 99328 B (2 CTAs/SM)
    constexpr int SM_ATTN = 1024 + 16384 + 2 * 32768;    // 82944 B
    cudaFuncSetAttribute(gemm_tma<0>, cudaFuncAttributeMaxDynamicSharedMemorySize, SM_TMA);
    cudaFuncSetAttribute(gemm_tma<1>, cudaFuncAttributeMaxDynamicSharedMemorySize, SM_TMA);
    cudaFuncSetAttribute(attn_kernel, cudaFuncAttributeMaxDynamicSharedMemorySize, SM_ATTN);

    // [0] pack
    pack_kernel<<<PB_TOTAL, 256>>>(h_in, h_t, wq_comp, wqc_t, wq_up, wqu_t,
                                   wk, wv, wkv_t, out_w1, w1_t, out_w2, w2_t);

    // [1] hc = h @ wq_comp  -> half tiled (KT=32)
    gemm_tma<1><<<dim3(4, 32), 256, SM_TMA>>>(
        h_t, wqc_t, nullptr, hc_t, 32, 32, 32, 0, 0, 8, 0);

    // [2] q = hc @ wq_up    -> fp32 (KT=8)
    gemm_tma<0><<<dim3(16, 32), 256, SM_TMA>>>(
        hc_t, wqu_t, q, nullptr, 8, 8, 8, 0, 0, C_H * C_D, 0);

    // [3] kv = h @ wkv      -> fp32 (KT=32)
    gemm_tma<0><<<dim3(2, 32), 256, SM_TMA>>>(
        h_t, wkv_t, kv, nullptr, 32, 32, 32, 0, 0, 2 * C_D, 0);

    // [4] RoPE + RMSNorm -> fp16 swizzled q/k/v tiles
    {
        int warps = C_TOK * C_H + C_TOK;
        rope_kernel<<<(warps * 32 + 255) / 256, 256>>>(q, kv, q_norm_w, k_norm_w,
                                                       qsp, ksp, vsp);
    }

    // [5] flash attention -> att half tiled
    attn_kernel<<<dim3(32, 16, 2), 128, SM_ATTN>>>(qsp, ksp, vsp, sink, att_t);

    // [6] y1 = grouped att @ w1 -> half tiled (KT=8)
    gemm_tma<1><<<dim3(16, 32, C_G), 256, SM_TMA>>>(
        att_t, w1_t, nullptr, y1_t, 8, 32, 8, 8, 128, 128, 32);

    // [7] out = y1 @ out_w2 -> fp32 (KT=128)
    gemm_tma<0><<<dim3(16, 32), 256, SM_TMA>>>(
        y1_t, w2_t, out, nullptr, 128, 128, 128, 0, 0, C_HID, 0);
}